// round 13
// baseline (speedup 1.0000x reference)
#include <cuda_runtime.h>
#include <math.h>

#define NN 50000
#define EE 800000

// ---------------- scratch (device globals; zero-initialized at load) ---------
__device__ float g_pq    [NN * 128];
__device__ float g_dennum[NN * 128];
__device__ float g_h1    [NN * 128];
__device__ float g_x2    [NN * 128];
__device__ float g_xpl   [NN * 64];
__device__ float g_aggr  [NN * 64];
__device__ float g_sum[128], g_sumsq[128];
// CSR
__device__ int g_deg[NN];              // invariant: zero at kernel_launch entry
__device__ int g_off[NN + 1];
__device__ int g_cur[NN];
__device__ int g_adj[EE];
__device__ int g_bsum[64];

__device__ __forceinline__ float sigmoidf_(float v) { return 1.0f / (1.0f + __expf(-v)); }

typedef unsigned long long ull;

__device__ __forceinline__ ull pack2s(float a) {
    ull r;
    asm("mov.b64 %0, {%1, %1};" : "=l"(r) : "f"(a));
    return r;
}
__device__ __forceinline__ void unpack2(ull v, float& a, float& b) {
    asm("mov.b64 {%0, %1}, %2;" : "=f"(a), "=f"(b) : "l"(v));
}
__device__ __forceinline__ ull fma2(ull a, ull b, ull c) {
    ull r;
    asm("fma.rn.f32x2 %0, %1, %2, %3;" : "=l"(r) : "l"(a), "l"(b), "l"(c));
    return r;
}

#define AT_S 68     // 64-node tiles (gemm1/gemm3)
#define AT_S2 132   // 128-node tiles (gemm2/gemm4)

// ---------------- prep (pq, sigmoid(x)) + degree histogram --------------------
__global__ void k_prep(const float* __restrict__ x, const int* __restrict__ dst,
                       int n, int E) {
    int tid = blockIdx.x * blockDim.x + threadIdx.x;
    if (tid < E) atomicAdd(&g_deg[dst[tid]], 1);
    if (tid >= n * 16) return;
    int nd = tid >> 4, c = tid & 15;
    float4 v = ((const float4*)x)[(size_t)nd * 16 + c];
    float m0 = fmaxf(v.x, 0.f) + 1e-7f;
    float m1 = fmaxf(v.y, 0.f) + 1e-7f;
    float m2 = fmaxf(v.z, 0.f) + 1e-7f;
    float m3 = fmaxf(v.w, 0.f) + 1e-7f;
    float p0 = expf(m0), p1 = expf(m1), p2 = expf(m2), p3 = expf(m3);
    float4* row = (float4*)&g_pq[(size_t)nd * 128];
    row[c]      = make_float4(p0, p1, p2, p3);
    row[16 + c] = make_float4(p0 * m0, p1 * m1, p2 * m2, p3 * m3);
    ((float4*)&g_x2[(size_t)nd * 128])[c] =
        make_float4(sigmoidf_(v.x), sigmoidf_(v.y), sigmoidf_(v.z), sigmoidf_(v.w));
}

// ---------------- scanA: per-block prefix of deg ------------------------------
__global__ void __launch_bounds__(1024) k_scanA(int n) {
    __shared__ int wp[32];
    int t = threadIdx.x, lane = t & 31, wid = t >> 5;
    int node = blockIdx.x * 1024 + t;
    int d = (node < n) ? g_deg[node] : 0;
    int inc = d;
#pragma unroll
    for (int s = 1; s < 32; s <<= 1) {
        int v = __shfl_up_sync(0xffffffffu, inc, s);
        if (lane >= s) inc += v;
    }
    if (lane == 31) wp[wid] = inc;
    __syncthreads();
    if (wid == 0) {
        int w = wp[lane], winc = w;
#pragma unroll
        for (int s = 1; s < 32; s <<= 1) {
            int v = __shfl_up_sync(0xffffffffu, winc, s);
            if (lane >= s) winc += v;
        }
        wp[lane] = winc - w;
    }
    __syncthreads();
    int ex = wp[wid] + inc - d;
    if (node < n) g_off[node] = ex;
    if (t == 1023) g_bsum[blockIdx.x] = ex + d;
}

// ---------------- scanC: inline block-offset combine + zero BN stats ----------
__global__ void __launch_bounds__(1024) k_scanC(int n, int E) {
    __shared__ int wsum[2];
    int t = threadIdx.x, b = blockIdx.x;
    int v = (t < b) ? g_bsum[t] : 0;   // b <= 49 < 64
#pragma unroll
    for (int s = 16; s; s >>= 1) v += __shfl_xor_sync(0xffffffffu, v, s);
    if (t == 0) wsum[0] = v;
    if (t == 32) wsum[1] = v;
    if (b == 0) {
        if (t == 0) g_off[n] = E;
        if (t < 128) { g_sum[t] = 0.f; g_sumsq[t] = 0.f; }
    }
    __syncthreads();
    int boff = wsum[0] + wsum[1];
    int node = b * 1024 + t;
    if (node < n) {
        int o = g_off[node] + boff;
        g_off[node] = o;
        g_cur[node] = o;
    }
}

__global__ void k_scatter(const int* __restrict__ src, const int* __restrict__ dst, int E) {
    int e = blockIdx.x * blockDim.x + threadIdx.x;
    if (e >= E) return;
    int pos = atomicAdd(&g_cur[dst[e]], 1);
    g_adj[pos] = src[e];
}

// ---------------- gathers (separate, high-occupancy) ---------------------------
__global__ void k_gather_gen(int n) {
    int w = (blockIdx.x * blockDim.x + threadIdx.x) >> 5;
    int lane = threadIdx.x & 31;
    if (w >= n) return;
    if (lane == 0) g_deg[w] = 0;
    int e = g_off[w], end = g_off[w + 1];
    float4 acc = make_float4(0.f, 0.f, 0.f, 0.f);
    for (; e + 4 <= end; e += 4) {
        int s0 = g_adj[e], s1 = g_adj[e + 1], s2 = g_adj[e + 2], s3 = g_adj[e + 3];
        float4 v0 = ((const float4*)g_pq)[(size_t)s0 * 32 + lane];
        float4 v1 = ((const float4*)g_pq)[(size_t)s1 * 32 + lane];
        float4 v2 = ((const float4*)g_pq)[(size_t)s2 * 32 + lane];
        float4 v3 = ((const float4*)g_pq)[(size_t)s3 * 32 + lane];
        acc.x += v0.x + v1.x + v2.x + v3.x;
        acc.y += v0.y + v1.y + v2.y + v3.y;
        acc.z += v0.z + v1.z + v2.z + v3.z;
        acc.w += v0.w + v1.w + v2.w + v3.w;
    }
    for (; e < end; e++) {
        int s = g_adj[e];
        float4 v = ((const float4*)g_pq)[(size_t)s * 32 + lane];
        acc.x += v.x; acc.y += v.y; acc.z += v.z; acc.w += v.w;
    }
    ((float4*)g_dennum)[(size_t)w * 32 + lane] = acc;
}

__global__ void k_gather_sage(int n) {
    int w = (blockIdx.x * blockDim.x + threadIdx.x) >> 4;
    int lane = threadIdx.x & 15;
    if (w >= n) return;
    int e = g_off[w], end = g_off[w + 1];
    float4 acc = make_float4(0.f, 0.f, 0.f, 0.f);
    for (; e + 4 <= end; e += 4) {
        int s0 = g_adj[e], s1 = g_adj[e + 1], s2 = g_adj[e + 2], s3 = g_adj[e + 3];
        float4 v0 = ((const float4*)g_xpl)[(size_t)s0 * 16 + lane];
        float4 v1 = ((const float4*)g_xpl)[(size_t)s1 * 16 + lane];
        float4 v2 = ((const float4*)g_xpl)[(size_t)s2 * 16 + lane];
        float4 v3 = ((const float4*)g_xpl)[(size_t)s3 * 16 + lane];
        acc.x += v0.x + v1.x + v2.x + v3.x;
        acc.y += v0.y + v1.y + v2.y + v3.y;
        acc.z += v0.z + v1.z + v2.z + v3.z;
        acc.w += v0.w + v1.w + v2.w + v3.w;
    }
    for (; e < end; e++) {
        int s = g_adj[e];
        float4 v = ((const float4*)g_xpl)[(size_t)s * 16 + lane];
        acc.x += v.x; acc.y += v.y; acc.z += v.z; acc.w += v.w;
    }
    ((float4*)g_aggr)[(size_t)w * 16 + lane] = acc;
}

// ============ tiled GEMM bodies (packed f32x2) ===============================
#define DECL_ACC2(CGMASK, NGSHIFT)                                              \
    int cg = tid & (CGMASK);                                                    \
    int ng = tid >> (NGSHIFT);                                                  \
    ull acc2[4][4];                                                             \
    _Pragma("unroll")                                                           \
    for (int i = 0; i < 4; i++)                                                 \
        _Pragma("unroll")                                                       \
        for (int j = 0; j < 4; j++) acc2[i][j] = 0ull;

#define MLBODY2S(CIN, COUT, STRIDE)                                             \
    {                                                                           \
        const float* Ap = At + ng * 4;                                          \
        const ull* Wq = (const ull*)(Ws + cg * 8);                              \
        _Pragma("unroll 8")                                                     \
        for (int k = 0; k < (CIN); k++) {                                       \
            float4 a4 = *(const float4*)&Ap[k * (STRIDE)];                      \
            ulonglong2 wa = *(const ulonglong2*)(Wq + k * ((COUT) / 2));        \
            ulonglong2 wb = *(const ulonglong2*)(Wq + k * ((COUT) / 2) + 2);    \
            ull av[4] = {pack2s(a4.x), pack2s(a4.y), pack2s(a4.z), pack2s(a4.w)};\
            _Pragma("unroll")                                                   \
            for (int i = 0; i < 4; i++) {                                       \
                acc2[i][0] = fma2(av[i], wa.x, acc2[i][0]);                     \
                acc2[i][1] = fma2(av[i], wa.y, acc2[i][1]);                     \
                acc2[i][2] = fma2(av[i], wb.x, acc2[i][2]);                     \
                acc2[i][3] = fma2(av[i], wb.y, acc2[i][3]);                     \
            }                                                                   \
        }                                                                       \
    }

#define UNPACK_ACC()                                                            \
    float acc[4][8];                                                            \
    _Pragma("unroll")                                                           \
    for (int i = 0; i < 4; i++)                                                 \
        _Pragma("unroll")                                                       \
        for (int j = 0; j < 4; j++)                                             \
            unpack2(acc2[i][j], acc[i][2 * j], acc[i][2 * j + 1]);

// ---------------- GEMM1 (+fused column stats); 64-node tile, 256 thr ----------
__global__ void __launch_bounds__(256) k_gemm1(const float* __restrict__ x,
                                               const float* __restrict__ W1,
                                               const float* __restrict__ b1, int n) {
    extern __shared__ float sm[];
    float* Ws = sm;
    float* At = Ws + 64 * 128;
    float* bs = At + 64 * AT_S;
    int tid = threadIdx.x;
    for (int i = tid; i < 2048; i += 256) ((float4*)Ws)[i] = ((const float4*)W1)[i];
    if (tid < 128) bs[tid] = b1[tid];
    int base = blockIdx.x * 64;
    for (int i = tid; i < 1024; i += 256) {
        int ndl = i >> 4, c4 = i & 15;
        int nd = base + ndl;
        float4 in4 = make_float4(0.f, 0.f, 0.f, 0.f);
        if (nd < n) {
            float4 de = ((const float4*)&g_dennum[(size_t)nd * 128])[c4];
            float4 nu = ((const float4*)&g_dennum[(size_t)nd * 128])[16 + c4];
            float4 xv = ((const float4*)x)[(size_t)nd * 16 + c4];
            in4.x = nu.x / (de.x > 0.f ? de.x : 1.f) + xv.x;
            in4.y = nu.y / (de.y > 0.f ? de.y : 1.f) + xv.y;
            in4.z = nu.z / (de.z > 0.f ? de.z : 1.f) + xv.z;
            in4.w = nu.w / (de.w > 0.f ? de.w : 1.f) + xv.w;
        }
        int k0 = c4 * 4;
        At[(k0 + 0) * AT_S + ndl] = in4.x;
        At[(k0 + 1) * AT_S + ndl] = in4.y;
        At[(k0 + 2) * AT_S + ndl] = in4.z;
        At[(k0 + 3) * AT_S + ndl] = in4.w;
    }
    __syncthreads();
    DECL_ACC2(15, 4)
    MLBODY2S(64, 128, AT_S)
    UNPACK_ACC()
    float ls[8], lq[8];
#pragma unroll
    for (int j = 0; j < 8; j++) { ls[j] = 0.f; lq[j] = 0.f; }
#pragma unroll
    for (int i = 0; i < 4; i++) {
        int nd = base + ng * 4 + i;
        if (nd >= n) break;
        float v[8];
#pragma unroll
        for (int j = 0; j < 8; j++) {
            v[j] = acc[i][j] + bs[cg * 8 + j];
            ls[j] += v[j];
            lq[j] += v[j] * v[j];
        }
        float4* o = (float4*)&g_h1[(size_t)nd * 128 + cg * 8];
        o[0] = make_float4(v[0], v[1], v[2], v[3]);
        o[1] = make_float4(v[4], v[5], v[6], v[7]);
    }
    __syncthreads();
    float* ssum = At;
    float* ssq  = At + 128;
    if (tid < 128) { ssum[tid] = 0.f; ssq[tid] = 0.f; }
    __syncthreads();
#pragma unroll
    for (int j = 0; j < 8; j++) {
        atomicAdd(&ssum[cg * 8 + j], ls[j]);
        atomicAdd(&ssq[cg * 8 + j], lq[j]);
    }
    __syncthreads();
    if (tid < 128) {
        atomicAdd(&g_sum[tid], ssum[tid]);
        atomicAdd(&g_sumsq[tid], ssq[tid]);
    }
}

// ---------------- GEMM2: 128-node tile, 256 threads ----------------------------
__global__ void __launch_bounds__(256) k_gemm2(const float* __restrict__ gamma,
                                               const float* __restrict__ beta,
                                               const float* __restrict__ W2,
                                               const float* __restrict__ b2, int n) {
    extern __shared__ float sm[];
    float* Ws = sm;                 // 128*64
    float* At = Ws + 128 * 64;      // 128*AT_S2
    float* prm = At + 128 * AT_S2;  // 4*128
    float* bs = prm + 512;          // 64
    int tid = threadIdx.x;
    for (int i = tid; i < 2048; i += 256) ((float4*)Ws)[i] = ((const float4*)W2)[i];
    if (tid < 128) {
        prm[tid]       = gamma[tid];
        prm[128 + tid] = beta[tid];
        float fn = (float)n;
        float mu = g_sum[tid] / fn;
        float var = g_sumsq[tid] / fn - mu * mu;
        prm[256 + tid] = mu;
        prm[384 + tid] = rsqrtf(var + 1e-5f);
    }
    if (tid < 64) bs[tid] = b2[tid];
    __syncthreads();
    int base = blockIdx.x * 128;
    for (int i = tid; i < 4096; i += 256) {
        int ndl = i >> 5, c4 = i & 31;
        int nd = base + ndl;
        float4 v = make_float4(0.f, 0.f, 0.f, 0.f);
        if (nd < n) v = ((const float4*)&g_h1[(size_t)nd * 128])[c4];
        int k0 = c4 * 4;
#pragma unroll
        for (int q = 0; q < 4; q++) {
            float val = (q == 0) ? v.x : (q == 1) ? v.y : (q == 2) ? v.z : v.w;
            int col = k0 + q;
            val = (val - prm[256 + col]) * prm[384 + col] * prm[col] + prm[128 + col];
            At[col * AT_S2 + ndl] = fmaxf(val, 0.f);
        }
    }
    __syncthreads();
    DECL_ACC2(7, 3)
    MLBODY2S(128, 64, AT_S2)
    UNPACK_ACC()
#pragma unroll
    for (int i = 0; i < 4; i++) {
        int nd = base + ng * 4 + i;
        if (nd >= n) break;
        float4 o0 = make_float4(sigmoidf_(acc[i][0] + bs[cg * 8 + 0]),
                                sigmoidf_(acc[i][1] + bs[cg * 8 + 1]),
                                sigmoidf_(acc[i][2] + bs[cg * 8 + 2]),
                                sigmoidf_(acc[i][3] + bs[cg * 8 + 3]));
        float4 o1 = make_float4(sigmoidf_(acc[i][4] + bs[cg * 8 + 4]),
                                sigmoidf_(acc[i][5] + bs[cg * 8 + 5]),
                                sigmoidf_(acc[i][6] + bs[cg * 8 + 6]),
                                sigmoidf_(acc[i][7] + bs[cg * 8 + 7]));
        float4* o = (float4*)&g_x2[(size_t)nd * 128 + 64 + cg * 8];
        o[0] = o0; o[1] = o1;
    }
}

// ---------------- GEMM3: xp = relu(x2@Wp+bp); xpl = xp@Wl ----------------------
__global__ void __launch_bounds__(256) k_gemm3(const float* __restrict__ Wp,
                                               const float* __restrict__ bp,
                                               const float* __restrict__ Wl, int n) {
    extern __shared__ float sm[];
    float* Ws = sm;                // 128*128 (Wp), stage2: first 128*64 = Wl
    float* At = Ws + 128 * 128;    // 128*AT_S
    float* bs = At + 128 * AT_S;   // 128
    int tid = threadIdx.x;
    for (int i = tid; i < 4096; i += 256) ((float4*)Ws)[i] = ((const float4*)Wp)[i];
    if (tid < 128) bs[tid] = bp[tid];
    int base = blockIdx.x * 64;
    for (int i = tid; i < 2048; i += 256) {
        int ndl = i >> 5, c4 = i & 31;
        int nd = base + ndl;
        float4 v = make_float4(0.f, 0.f, 0.f, 0.f);
        if (nd < n) v = ((const float4*)&g_x2[(size_t)nd * 128])[c4];
        int k0 = c4 * 4;
        At[(k0 + 0) * AT_S + ndl] = v.x;
        At[(k0 + 1) * AT_S + ndl] = v.y;
        At[(k0 + 2) * AT_S + ndl] = v.z;
        At[(k0 + 3) * AT_S + ndl] = v.w;
    }
    __syncthreads();
    DECL_ACC2(15, 4)
    MLBODY2S(128, 128, AT_S)
    UNPACK_ACC()
    float xpv[4][8];
#pragma unroll
    for (int i = 0; i < 4; i++)
#pragma unroll
        for (int j = 0; j < 8; j++)
            xpv[i][j] = fmaxf(acc[i][j] + bs[cg * 8 + j], 0.f);
    __syncthreads();
    for (int i = tid; i < 2048; i += 256) ((float4*)Ws)[i] = ((const float4*)Wl)[i];
#pragma unroll
    for (int i = 0; i < 4; i++)
#pragma unroll
        for (int j = 0; j < 8; j++)
            At[(cg * 8 + j) * AT_S + (ng * 4 + i)] = xpv[i][j];
    __syncthreads();
    int cg2 = tid & 7, ng2 = tid >> 3;
    ull a2[2][4];
#pragma unroll
    for (int i = 0; i < 2; i++)
#pragma unroll
        for (int j = 0; j < 4; j++) a2[i][j] = 0ull;
    {
        const float* Ap2 = At + ng2 * 2;
        const ull* Wq2 = (const ull*)(Ws + cg2 * 8);
#pragma unroll 8
        for (int k = 0; k < 128; k++) {
            float2 a = *(const float2*)&Ap2[k * AT_S];
            ulonglong2 wa = *(const ulonglong2*)(Wq2 + k * 32);
            ulonglong2 wb = *(const ulonglong2*)(Wq2 + k * 32 + 2);
            ull av0 = pack2s(a.x), av1 = pack2s(a.y);
            a2[0][0] = fma2(av0, wa.x, a2[0][0]);
            a2[0][1] = fma2(av0, wa.y, a2[0][1]);
            a2[0][2] = fma2(av0, wb.x, a2[0][2]);
            a2[0][3] = fma2(av0, wb.y, a2[0][3]);
            a2[1][0] = fma2(av1, wa.x, a2[1][0]);
            a2[1][1] = fma2(av1, wa.y, a2[1][1]);
            a2[1][2] = fma2(av1, wb.x, a2[1][2]);
            a2[1][3] = fma2(av1, wb.y, a2[1][3]);
        }
    }
#pragma unroll
    for (int i = 0; i < 2; i++) {
        int nd = base + ng2 * 2 + i;
        if (nd >= n) break;
        float v[8];
#pragma unroll
        for (int j = 0; j < 4; j++) unpack2(a2[i][j], v[2 * j], v[2 * j + 1]);
        float4* o = (float4*)&g_xpl[(size_t)nd * 64 + cg2 * 8];
        o[0] = make_float4(v[0], v[1], v[2], v[3]);
        o[1] = make_float4(v[4], v[5], v[6], v[7]);
    }
}

// ---------------- GEMM4: 128-node tile, 256 threads ----------------------------
__global__ void __launch_bounds__(256) k_gemm4(const float* __restrict__ Wr,
                                               const float* __restrict__ bl,
                                               const float* __restrict__ Wf,
                                               const float* __restrict__ bf,
                                               float* __restrict__ out,
                                               int n, int write_logits) {
    extern __shared__ float sm[];
    float* Ws = sm;                 // 128*64
    float* At = Ws + 128 * 64;      // 128*AT_S2
    float* bs = At + 128 * AT_S2;   // 64
    float* wf = bs + 64;            // 64
    int tid = threadIdx.x;
    int base = blockIdx.x * 128;
    for (int i = tid; i < 2048; i += 256) ((float4*)Ws)[i] = ((const float4*)Wr)[i];
    if (tid < 64) { bs[tid] = bl[tid]; wf[tid] = Wf[tid]; }
    for (int i = tid; i < 4096; i += 256) {
        int ndl = i >> 5, c4 = i & 31;
        int nd = base + ndl;
        float4 v = make_float4(0.f, 0.f, 0.f, 0.f);
        if (nd < n) v = ((const float4*)&g_x2[(size_t)nd * 128])[c4];
        int k0 = c4 * 4;
        At[(k0 + 0) * AT_S2 + ndl] = v.x;
        At[(k0 + 1) * AT_S2 + ndl] = v.y;
        At[(k0 + 2) * AT_S2 + ndl] = v.z;
        At[(k0 + 3) * AT_S2 + ndl] = v.w;
    }
    __syncthreads();
    DECL_ACC2(7, 3)
    MLBODY2S(128, 64, AT_S2)
    UNPACK_ACC()
    float bf0 = bf[0];
#pragma unroll
    for (int i = 0; i < 4; i++) {
        int nd = base + ng * 4 + i;
        float lp = 0.f;
        if (nd < n) {
            float4 a0 = ((const float4*)&g_aggr[(size_t)nd * 64 + cg * 8])[0];
            float4 a1 = ((const float4*)&g_aggr[(size_t)nd * 64 + cg * 8])[1];
            float av[8] = {a0.x, a0.y, a0.z, a0.w, a1.x, a1.y, a1.z, a1.w};
#pragma unroll
            for (int j = 0; j < 8; j++)
                lp += sigmoidf_(acc[i][j] + av[j] + bs[cg * 8 + j]) * wf[cg * 8 + j];
        }
        lp += __shfl_xor_sync(0xffffffffu, lp, 1);
        lp += __shfl_xor_sync(0xffffffffu, lp, 2);
        lp += __shfl_xor_sync(0xffffffffu, lp, 4);
        if (cg == 0 && nd < n) {
            float logit = lp + bf0;
            out[nd] = sigmoidf_(logit);
            if (write_logits) out[n + nd] = logit;
        }
    }
}

// ---------------- launch --------------------------------------------------------
extern "C" void kernel_launch(void* const* d_in, const int* in_sizes, int n_in,
                              void* d_out, int out_size) {
    const float* x   = (const float*)d_in[0];
    const int*   ei  = (const int*)d_in[1];
    const float* W1  = (const float*)d_in[2];
    const float* b1  = (const float*)d_in[3];
    const float* gamma = (const float*)d_in[4];
    const float* beta  = (const float*)d_in[5];
    const float* W2  = (const float*)d_in[6];
    const float* b2  = (const float*)d_in[7];
    const float* Wp  = (const float*)d_in[8];
    const float* bp  = (const float*)d_in[9];
    const float* Wl  = (const float*)d_in[10];
    const float* bl  = (const float*)d_in[11];
    const float* Wr  = (const float*)d_in[12];
    const float* Wf  = (const float*)d_in[13];
    const float* bf  = (const float*)d_in[14];
    float* out = (float*)d_out;

    int n = in_sizes[0] / 64;
    int E = in_sizes[1] / 2;
    const int* src = ei;
    const int* dst = ei + E;
    int write_logits = (out_size >= 2 * n) ? 1 : 0;

    const int S1 = (64 * 128 + 64 * AT_S + 128) * 4;
    const int S2 = (128 * 64 + 128 * AT_S2 + 512 + 64) * 4;
    const int S3 = (128 * 128 + 128 * AT_S + 128) * 4;
    const int S4 = (128 * 64 + 128 * AT_S2 + 128) * 4;
    cudaFuncSetAttribute(k_gemm1, cudaFuncAttributeMaxDynamicSharedMemorySize, S1);
    cudaFuncSetAttribute(k_gemm2, cudaFuncAttributeMaxDynamicSharedMemorySize, S2);
    cudaFuncSetAttribute(k_gemm3, cudaFuncAttributeMaxDynamicSharedMemorySize, S3);
    cudaFuncSetAttribute(k_gemm4, cudaFuncAttributeMaxDynamicSharedMemorySize, S4);

    int tmax = (n * 16 > E) ? n * 16 : E;
    k_prep<<<(tmax + 255) / 256, 256>>>(x, dst, n, E);
    int nb1024 = (n + 1023) / 1024;
    k_scanA<<<nb1024, 1024>>>(n);
    k_scanC<<<nb1024, 1024>>>(n, E);
    k_scatter<<<(E + 255) / 256, 256>>>(src, dst, E);

    k_gather_gen<<<(n * 32 + 255) / 256, 256>>>(n);

    int nb64 = (n + 63) / 64;
    int nb128 = (n + 127) / 128;
    k_gemm1<<<nb64, 256, S1>>>(x, W1, b1, n);
    k_gemm2<<<nb128, 256, S2>>>(gamma, beta, W2, b2, n);
    k_gemm3<<<nb64, 256, S3>>>(Wp, bp, Wl, n);
    k_gather_sage<<<(n * 16 + 255) / 256, 256>>>(n);
    k_gemm4<<<nb128, 256, S4>>>(Wr, bl, Wf, bf, out, n, write_logits);
}

// round 14
// speedup vs baseline: 1.0360x; 1.0360x over previous
#include <cuda_runtime.h>
#include <math.h>

#define NN 50000
#define EE 800000

// ---------------- scratch (device globals; zero-initialized at load) ---------
__device__ float g_pq    [NN * 128];
__device__ float g_dennum[NN * 128];
__device__ float g_h1    [NN * 128];
__device__ float g_x2    [NN * 128];
__device__ float g_xpl   [NN * 64];    // xp @ Wl
__device__ float g_xr    [NN * 64];    // x2 @ Wr
__device__ float g_aggr  [NN * 64];
__device__ float g_sum[128], g_sumsq[128];
// CSR
__device__ int g_deg[NN];              // invariant: zero at kernel_launch entry
__device__ int g_off[NN + 1];
__device__ int g_cur[NN];
__device__ int g_adj[EE];
__device__ int g_bsum[64];

__device__ __forceinline__ float sigmoidf_(float v) { return 1.0f / (1.0f + __expf(-v)); }

typedef unsigned long long ull;

__device__ __forceinline__ ull pack2s(float a) {
    ull r;
    asm("mov.b64 %0, {%1, %1};" : "=l"(r) : "f"(a));
    return r;
}
__device__ __forceinline__ void unpack2(ull v, float& a, float& b) {
    asm("mov.b64 {%0, %1}, %2;" : "=f"(a), "=f"(b) : "l"(v));
}
__device__ __forceinline__ ull fma2(ull a, ull b, ull c) {
    ull r;
    asm("fma.rn.f32x2 %0, %1, %2, %3;" : "=l"(r) : "l"(a), "l"(b), "l"(c));
    return r;
}

#define AT_S 68

// ---------------- prep (pq, sigmoid(x)) + degree histogram --------------------
__global__ void k_prep(const float* __restrict__ x, const int* __restrict__ dst,
                       int n, int E) {
    int tid = blockIdx.x * blockDim.x + threadIdx.x;
    if (tid < E) atomicAdd(&g_deg[dst[tid]], 1);
    if (tid >= n * 16) return;
    int nd = tid >> 4, c = tid & 15;
    float4 v = ((const float4*)x)[(size_t)nd * 16 + c];
    float m0 = fmaxf(v.x, 0.f) + 1e-7f;
    float m1 = fmaxf(v.y, 0.f) + 1e-7f;
    float m2 = fmaxf(v.z, 0.f) + 1e-7f;
    float m3 = fmaxf(v.w, 0.f) + 1e-7f;
    float p0 = expf(m0), p1 = expf(m1), p2 = expf(m2), p3 = expf(m3);
    float4* row = (float4*)&g_pq[(size_t)nd * 128];
    row[c]      = make_float4(p0, p1, p2, p3);
    row[16 + c] = make_float4(p0 * m0, p1 * m1, p2 * m2, p3 * m3);
    ((float4*)&g_x2[(size_t)nd * 128])[c] =
        make_float4(sigmoidf_(v.x), sigmoidf_(v.y), sigmoidf_(v.z), sigmoidf_(v.w));
}

// ---------------- scanA ---------------------------------------------------------
__global__ void __launch_bounds__(1024) k_scanA(int n) {
    __shared__ int wp[32];
    int t = threadIdx.x, lane = t & 31, wid = t >> 5;
    int node = blockIdx.x * 1024 + t;
    int d = (node < n) ? g_deg[node] : 0;
    int inc = d;
#pragma unroll
    for (int s = 1; s < 32; s <<= 1) {
        int v = __shfl_up_sync(0xffffffffu, inc, s);
        if (lane >= s) inc += v;
    }
    if (lane == 31) wp[wid] = inc;
    __syncthreads();
    if (wid == 0) {
        int w = wp[lane], winc = w;
#pragma unroll
        for (int s = 1; s < 32; s <<= 1) {
            int v = __shfl_up_sync(0xffffffffu, winc, s);
            if (lane >= s) winc += v;
        }
        wp[lane] = winc - w;
    }
    __syncthreads();
    int ex = wp[wid] + inc - d;
    if (node < n) g_off[node] = ex;
    if (t == 1023) g_bsum[blockIdx.x] = ex + d;
}

// ---------------- scanC: inline block-offset combine + zero BN stats ----------
__global__ void __launch_bounds__(1024) k_scanC(int n, int E) {
    __shared__ int wsum[2];
    int t = threadIdx.x, b = blockIdx.x;
    int v = (t < b) ? g_bsum[t] : 0;   // b <= 49 < 64
#pragma unroll
    for (int s = 16; s; s >>= 1) v += __shfl_xor_sync(0xffffffffu, v, s);
    if (t == 0) wsum[0] = v;
    if (t == 32) wsum[1] = v;
    if (b == 0) {
        if (t == 0) g_off[n] = E;
        if (t < 128) { g_sum[t] = 0.f; g_sumsq[t] = 0.f; }
    }
    __syncthreads();
    int boff = wsum[0] + wsum[1];
    int node = b * 1024 + t;
    if (node < n) {
        int o = g_off[node] + boff;
        g_off[node] = o;
        g_cur[node] = o;
    }
}

__global__ void k_scatter(const int* __restrict__ src, const int* __restrict__ dst, int E) {
    int e = blockIdx.x * blockDim.x + threadIdx.x;
    if (e >= E) return;
    int pos = atomicAdd(&g_cur[dst[e]], 1);
    g_adj[pos] = src[e];
}

// ---------------- gathers -------------------------------------------------------
__global__ void k_gather_gen(int n) {
    int w = (blockIdx.x * blockDim.x + threadIdx.x) >> 5;
    int lane = threadIdx.x & 31;
    if (w >= n) return;
    if (lane == 0) g_deg[w] = 0;
    int e = g_off[w], end = g_off[w + 1];
    float4 acc = make_float4(0.f, 0.f, 0.f, 0.f);
    for (; e + 4 <= end; e += 4) {
        int s0 = g_adj[e], s1 = g_adj[e + 1], s2 = g_adj[e + 2], s3 = g_adj[e + 3];
        float4 v0 = ((const float4*)g_pq)[(size_t)s0 * 32 + lane];
        float4 v1 = ((const float4*)g_pq)[(size_t)s1 * 32 + lane];
        float4 v2 = ((const float4*)g_pq)[(size_t)s2 * 32 + lane];
        float4 v3 = ((const float4*)g_pq)[(size_t)s3 * 32 + lane];
        acc.x += v0.x + v1.x + v2.x + v3.x;
        acc.y += v0.y + v1.y + v2.y + v3.y;
        acc.z += v0.z + v1.z + v2.z + v3.z;
        acc.w += v0.w + v1.w + v2.w + v3.w;
    }
    for (; e < end; e++) {
        int s = g_adj[e];
        float4 v = ((const float4*)g_pq)[(size_t)s * 32 + lane];
        acc.x += v.x; acc.y += v.y; acc.z += v.z; acc.w += v.w;
    }
    ((float4*)g_dennum)[(size_t)w * 32 + lane] = acc;
}

__global__ void k_gather_sage(int n) {
    int w = (blockIdx.x * blockDim.x + threadIdx.x) >> 4;
    int lane = threadIdx.x & 15;
    if (w >= n) return;
    int e = g_off[w], end = g_off[w + 1];
    float4 acc = make_float4(0.f, 0.f, 0.f, 0.f);
    for (; e + 4 <= end; e += 4) {
        int s0 = g_adj[e], s1 = g_adj[e + 1], s2 = g_adj[e + 2], s3 = g_adj[e + 3];
        float4 v0 = ((const float4*)g_xpl)[(size_t)s0 * 16 + lane];
        float4 v1 = ((const float4*)g_xpl)[(size_t)s1 * 16 + lane];
        float4 v2 = ((const float4*)g_xpl)[(size_t)s2 * 16 + lane];
        float4 v3 = ((const float4*)g_xpl)[(size_t)s3 * 16 + lane];
        acc.x += v0.x + v1.x + v2.x + v3.x;
        acc.y += v0.y + v1.y + v2.y + v3.y;
        acc.z += v0.z + v1.z + v2.z + v3.z;
        acc.w += v0.w + v1.w + v2.w + v3.w;
    }
    for (; e < end; e++) {
        int s = g_adj[e];
        float4 v = ((const float4*)g_xpl)[(size_t)s * 16 + lane];
        acc.x += v.x; acc.y += v.y; acc.z += v.z; acc.w += v.w;
    }
    ((float4*)g_aggr)[(size_t)w * 16 + lane] = acc;
}

// ============ tiled GEMM bodies (packed f32x2) ===============================
#define DECL_ACC2(CGMASK, NGSHIFT)                                              \
    int cg = tid & (CGMASK);                                                    \
    int ng = tid >> (NGSHIFT);                                                  \
    ull acc2[4][4];                                                             \
    _Pragma("unroll")                                                           \
    for (int i = 0; i < 4; i++)                                                 \
        _Pragma("unroll")                                                       \
        for (int j = 0; j < 4; j++) acc2[i][j] = 0ull;

#define MLBODY2(CIN, COUT)                                                      \
    {                                                                           \
        const float* Ap = At + ng * 4;                                          \
        const ull* Wq = (const ull*)(Ws + cg * 8);                              \
        _Pragma("unroll 8")                                                     \
        for (int k = 0; k < (CIN); k++) {                                       \
            float4 a4 = *(const float4*)&Ap[k * AT_S];                          \
            ulonglong2 wa = *(const ulonglong2*)(Wq + k * ((COUT) / 2));        \
            ulonglong2 wb = *(const ulonglong2*)(Wq + k * ((COUT) / 2) + 2);    \
            ull av[4] = {pack2s(a4.x), pack2s(a4.y), pack2s(a4.z), pack2s(a4.w)};\
            _Pragma("unroll")                                                   \
            for (int i = 0; i < 4; i++) {                                       \
                acc2[i][0] = fma2(av[i], wa.x, acc2[i][0]);                     \
                acc2[i][1] = fma2(av[i], wa.y, acc2[i][1]);                     \
                acc2[i][2] = fma2(av[i], wb.x, acc2[i][2]);                     \
                acc2[i][3] = fma2(av[i], wb.y, acc2[i][3]);                     \
            }                                                                   \
        }                                                                       \
    }

#define UNPACK_ACC()                                                            \
    float acc[4][8];                                                            \
    _Pragma("unroll")                                                           \
    for (int i = 0; i < 4; i++)                                                 \
        _Pragma("unroll")                                                       \
        for (int j = 0; j < 4; j++)                                             \
            unpack2(acc2[i][j], acc[i][2 * j], acc[i][2 * j + 1]);

// 64-out mainloop over 64-node At, 256 threads: 2 nodes x 8 cols per thread.
// Writes result to dstbuf[nd*64 + cg2*8].
#define MLBODY_64OUT(DSTBUF)                                                    \
    {                                                                           \
        int cg2 = tid & 7, ng2 = tid >> 3;                                      \
        ull a2[2][4];                                                           \
        _Pragma("unroll")                                                       \
        for (int i = 0; i < 2; i++)                                             \
            _Pragma("unroll")                                                   \
            for (int j = 0; j < 4; j++) a2[i][j] = 0ull;                        \
        const float* Ap2 = At + ng2 * 2;                                        \
        const ull* Wq2 = (const ull*)(Ws + cg2 * 8);                            \
        _Pragma("unroll 8")                                                     \
        for (int k = 0; k < 128; k++) {                                         \
            float2 a = *(const float2*)&Ap2[k * AT_S];                          \
            ulonglong2 wa = *(const ulonglong2*)(Wq2 + k * 32);                 \
            ulonglong2 wb = *(const ulonglong2*)(Wq2 + k * 32 + 2);             \
            ull av0 = pack2s(a.x), av1 = pack2s(a.y);                           \
            a2[0][0] = fma2(av0, wa.x, a2[0][0]);                               \
            a2[0][1] = fma2(av0, wa.y, a2[0][1]);                               \
            a2[0][2] = fma2(av0, wb.x, a2[0][2]);                               \
            a2[0][3] = fma2(av0, wb.y, a2[0][3]);                               \
            a2[1][0] = fma2(av1, wa.x, a2[1][0]);                               \
            a2[1][1] = fma2(av1, wa.y, a2[1][1]);                               \
            a2[1][2] = fma2(av1, wb.x, a2[1][2]);                               \
            a2[1][3] = fma2(av1, wb.y, a2[1][3]);                               \
        }                                                                       \
        _Pragma("unroll")                                                       \
        for (int i = 0; i < 2; i++) {                                           \
            int nd = base + ng2 * 2 + i;                                        \
            if (nd >= n) break;                                                 \
            float v[8];                                                         \
            _Pragma("unroll")                                                   \
            for (int j = 0; j < 4; j++) unpack2(a2[i][j], v[2*j], v[2*j+1]);    \
            float4* o = (float4*)&(DSTBUF)[(size_t)nd * 64 + cg2 * 8];          \
            o[0] = make_float4(v[0], v[1], v[2], v[3]);                         \
            o[1] = make_float4(v[4], v[5], v[6], v[7]);                         \
        }                                                                       \
    }

// ---------------- GEMM1 (+fused column stats) --------------------------------
__global__ void __launch_bounds__(256) k_gemm1(const float* __restrict__ x,
                                               const float* __restrict__ W1,
                                               const float* __restrict__ b1, int n) {
    extern __shared__ float sm[];
    float* Ws = sm;
    float* At = Ws + 64 * 128;
    float* bs = At + 64 * AT_S;
    int tid = threadIdx.x;
    for (int i = tid; i < 2048; i += 256) ((float4*)Ws)[i] = ((const float4*)W1)[i];
    if (tid < 128) bs[tid] = b1[tid];
    int base = blockIdx.x * 64;
    for (int i = tid; i < 1024; i += 256) {
        int ndl = i >> 4, c4 = i & 15;
        int nd = base + ndl;
        float4 in4 = make_float4(0.f, 0.f, 0.f, 0.f);
        if (nd < n) {
            float4 de = ((const float4*)&g_dennum[(size_t)nd * 128])[c4];
            float4 nu = ((const float4*)&g_dennum[(size_t)nd * 128])[16 + c4];
            float4 xv = ((const float4*)x)[(size_t)nd * 16 + c4];
            in4.x = nu.x / (de.x > 0.f ? de.x : 1.f) + xv.x;
            in4.y = nu.y / (de.y > 0.f ? de.y : 1.f) + xv.y;
            in4.z = nu.z / (de.z > 0.f ? de.z : 1.f) + xv.z;
            in4.w = nu.w / (de.w > 0.f ? de.w : 1.f) + xv.w;
        }
        int k0 = c4 * 4;
        At[(k0 + 0) * AT_S + ndl] = in4.x;
        At[(k0 + 1) * AT_S + ndl] = in4.y;
        At[(k0 + 2) * AT_S + ndl] = in4.z;
        At[(k0 + 3) * AT_S + ndl] = in4.w;
    }
    __syncthreads();
    DECL_ACC2(15, 4)
    MLBODY2(64, 128)
    UNPACK_ACC()
    float ls[8], lq[8];
#pragma unroll
    for (int j = 0; j < 8; j++) { ls[j] = 0.f; lq[j] = 0.f; }
#pragma unroll
    for (int i = 0; i < 4; i++) {
        int nd = base + ng * 4 + i;
        if (nd >= n) break;
        float v[8];
#pragma unroll
        for (int j = 0; j < 8; j++) {
            v[j] = acc[i][j] + bs[cg * 8 + j];
            ls[j] += v[j];
            lq[j] += v[j] * v[j];
        }
        float4* o = (float4*)&g_h1[(size_t)nd * 128 + cg * 8];
        o[0] = make_float4(v[0], v[1], v[2], v[3]);
        o[1] = make_float4(v[4], v[5], v[6], v[7]);
    }
    __syncthreads();
    float* ssum = At;
    float* ssq  = At + 128;
    if (tid < 128) { ssum[tid] = 0.f; ssq[tid] = 0.f; }
    __syncthreads();
#pragma unroll
    for (int j = 0; j < 8; j++) {
        atomicAdd(&ssum[cg * 8 + j], ls[j]);
        atomicAdd(&ssq[cg * 8 + j], lq[j]);
    }
    __syncthreads();
    if (tid < 128) {
        atomicAdd(&g_sum[tid], ssum[tid]);
        atomicAdd(&g_sumsq[tid], ssq[tid]);
    }
}

// ---------------- GEMM2 (BN stats inline) -------------------------------------
__global__ void __launch_bounds__(128) k_gemm2(const float* __restrict__ gamma,
                                               const float* __restrict__ beta,
                                               const float* __restrict__ W2,
                                               const float* __restrict__ b2, int n) {
    extern __shared__ float sm[];
    float* Ws = sm;
    float* At = Ws + 128 * 64;
    float* prm = At + 128 * AT_S;
    float* bs = prm + 512;
    int tid = threadIdx.x;
    for (int i = tid; i < 2048; i += 128) ((float4*)Ws)[i] = ((const float4*)W2)[i];
    if (tid < 128) {
        prm[tid]       = gamma[tid];
        prm[128 + tid] = beta[tid];
        float fn = (float)n;
        float mu = g_sum[tid] / fn;
        float var = g_sumsq[tid] / fn - mu * mu;
        prm[256 + tid] = mu;
        prm[384 + tid] = rsqrtf(var + 1e-5f);
    }
    if (tid < 64) bs[tid] = b2[tid];
    __syncthreads();
    int base = blockIdx.x * 64;
    for (int i = tid; i < 2048; i += 128) {
        int ndl = i >> 5, c4 = i & 31;
        int nd = base + ndl;
        float4 v = make_float4(0.f, 0.f, 0.f, 0.f);
        if (nd < n) v = ((const float4*)&g_h1[(size_t)nd * 128])[c4];
        int k0 = c4 * 4;
#pragma unroll
        for (int q = 0; q < 4; q++) {
            float val = (q == 0) ? v.x : (q == 1) ? v.y : (q == 2) ? v.z : v.w;
            int col = k0 + q;
            val = (val - prm[256 + col]) * prm[384 + col] * prm[col] + prm[128 + col];
            At[col * AT_S + ndl] = fmaxf(val, 0.f);
        }
    }
    __syncthreads();
    DECL_ACC2(7, 3)
    MLBODY2(128, 64)
    UNPACK_ACC()
#pragma unroll
    for (int i = 0; i < 4; i++) {
        int nd = base + ng * 4 + i;
        if (nd >= n) break;
        float4 o0 = make_float4(sigmoidf_(acc[i][0] + bs[cg * 8 + 0]),
                                sigmoidf_(acc[i][1] + bs[cg * 8 + 1]),
                                sigmoidf_(acc[i][2] + bs[cg * 8 + 2]),
                                sigmoidf_(acc[i][3] + bs[cg * 8 + 3]));
        float4 o1 = make_float4(sigmoidf_(acc[i][4] + bs[cg * 8 + 4]),
                                sigmoidf_(acc[i][5] + bs[cg * 8 + 5]),
                                sigmoidf_(acc[i][6] + bs[cg * 8 + 6]),
                                sigmoidf_(acc[i][7] + bs[cg * 8 + 7]));
        float4* o = (float4*)&g_x2[(size_t)nd * 128 + 64 + cg * 8];
        o[0] = o0; o[1] = o1;
    }
}

// ---------------- GEMM3: xp=relu(x2@Wp+bp); xr=x2@Wr; xpl=xp@Wl ----------------
__global__ void __launch_bounds__(256) k_gemm3(const float* __restrict__ Wp,
                                               const float* __restrict__ bp,
                                               const float* __restrict__ Wr,
                                               const float* __restrict__ Wl, int n) {
    extern __shared__ float sm[];
    float* Ws = sm;                // 128*128 (Wp); later 128*64 (Wr, then Wl)
    float* At = Ws + 128 * 128;    // 128*AT_S
    float* bs = At + 128 * AT_S;   // 128
    int tid = threadIdx.x;
    for (int i = tid; i < 4096; i += 256) ((float4*)Ws)[i] = ((const float4*)Wp)[i];
    if (tid < 128) bs[tid] = bp[tid];
    int base = blockIdx.x * 64;
    for (int i = tid; i < 2048; i += 256) {
        int ndl = i >> 5, c4 = i & 31;
        int nd = base + ndl;
        float4 v = make_float4(0.f, 0.f, 0.f, 0.f);
        if (nd < n) v = ((const float4*)&g_x2[(size_t)nd * 128])[c4];
        int k0 = c4 * 4;
        At[(k0 + 0) * AT_S + ndl] = v.x;
        At[(k0 + 1) * AT_S + ndl] = v.y;
        At[(k0 + 2) * AT_S + ndl] = v.z;
        At[(k0 + 3) * AT_S + ndl] = v.w;
    }
    __syncthreads();
    // stage 1: xp = x2 @ Wp (held in regs)
    DECL_ACC2(15, 4)
    MLBODY2(128, 128)
    UNPACK_ACC()
    float xpv[4][8];
#pragma unroll
    for (int i = 0; i < 4; i++)
#pragma unroll
        for (int j = 0; j < 8; j++)
            xpv[i][j] = fmaxf(acc[i][j] + bs[cg * 8 + j], 0.f);
    __syncthreads();   // all done reading Ws (Wp); At (x2) still needed
    // stage 2: xr = x2 @ Wr using the SAME At
    for (int i = tid; i < 2048; i += 256) ((float4*)Ws)[i] = ((const float4*)Wr)[i];
    __syncthreads();
    MLBODY_64OUT(g_xr)
    __syncthreads();   // done reading At (x2) and Ws (Wr)
    // stage 3: xpl = xp @ Wl; overwrite At with xp^T, Ws with Wl
    for (int i = tid; i < 2048; i += 256) ((float4*)Ws)[i] = ((const float4*)Wl)[i];
#pragma unroll
    for (int i = 0; i < 4; i++)
#pragma unroll
        for (int j = 0; j < 8; j++)
            At[(cg * 8 + j) * AT_S + (ng * 4 + i)] = xpv[i][j];
    __syncthreads();
    MLBODY_64OUT(g_xpl)
}

// ---------------- final: out = sigmoid( sigmoid(aggr + xr + bl) @ Wf + bf ) ----
__global__ void __launch_bounds__(256) k_final(const float* __restrict__ bl,
                                               const float* __restrict__ Wf,
                                               const float* __restrict__ bf,
                                               float* __restrict__ out,
                                               int n, int write_logits) {
    __shared__ float bs[64], wf[64];
    int tid = threadIdx.x;
    if (tid < 64) { bs[tid] = bl[tid]; wf[tid] = Wf[tid]; }
    __syncthreads();
    int idx = blockIdx.x * 256 + tid;
    int nd = idx >> 3, cg = idx & 7;
    float lp = 0.f;
    if (nd < n) {
        const float4* xr4 = (const float4*)&g_xr[(size_t)nd * 64 + cg * 8];
        const float4* ag4 = (const float4*)&g_aggr[(size_t)nd * 64 + cg * 8];
        float4 x0 = xr4[0], x1 = xr4[1], a0 = ag4[0], a1 = ag4[1];
        float xv[8] = {x0.x, x0.y, x0.z, x0.w, x1.x, x1.y, x1.z, x1.w};
        float av[8] = {a0.x, a0.y, a0.z, a0.w, a1.x, a1.y, a1.z, a1.w};
#pragma unroll
        for (int j = 0; j < 8; j++)
            lp += sigmoidf_(xv[j] + av[j] + bs[cg * 8 + j]) * wf[cg * 8 + j];
    }
    lp += __shfl_xor_sync(0xffffffffu, lp, 1);
    lp += __shfl_xor_sync(0xffffffffu, lp, 2);
    lp += __shfl_xor_sync(0xffffffffu, lp, 4);
    if (cg == 0 && nd < n) {
        float logit = lp + bf[0];
        out[nd] = sigmoidf_(logit);
        if (write_logits) out[n + nd] = logit;
    }
}

// ---------------- launch --------------------------------------------------------
extern "C" void kernel_launch(void* const* d_in, const int* in_sizes, int n_in,
                              void* d_out, int out_size) {
    const float* x   = (const float*)d_in[0];
    const int*   ei  = (const int*)d_in[1];
    const float* W1  = (const float*)d_in[2];
    const float* b1  = (const float*)d_in[3];
    const float* gamma = (const float*)d_in[4];
    const float* beta  = (const float*)d_in[5];
    const float* W2  = (const float*)d_in[6];
    const float* b2  = (const float*)d_in[7];
    const float* Wp  = (const float*)d_in[8];
    const float* bp  = (const float*)d_in[9];
    const float* Wl  = (const float*)d_in[10];
    const float* bl  = (const float*)d_in[11];
    const float* Wr  = (const float*)d_in[12];
    const float* Wf  = (const float*)d_in[13];
    const float* bf  = (const float*)d_in[14];
    float* out = (float*)d_out;

    int n = in_sizes[0] / 64;
    int E = in_sizes[1] / 2;
    const int* src = ei;
    const int* dst = ei + E;
    int write_logits = (out_size >= 2 * n) ? 1 : 0;

    const int S1 = (64 * 128 + 64 * AT_S + 128) * 4;
    const int S2 = (128 * 64 + 128 * AT_S + 512 + 64) * 4;
    const int S3 = (128 * 128 + 128 * AT_S + 128) * 4;
    cudaFuncSetAttribute(k_gemm1, cudaFuncAttributeMaxDynamicSharedMemorySize, S1);
    cudaFuncSetAttribute(k_gemm2, cudaFuncAttributeMaxDynamicSharedMemorySize, S2);
    cudaFuncSetAttribute(k_gemm3, cudaFuncAttributeMaxDynamicSharedMemorySize, S3);

    int tmax = (n * 16 > E) ? n * 16 : E;
    k_prep<<<(tmax + 255) / 256, 256>>>(x, dst, n, E);
    int nb1024 = (n + 1023) / 1024;
    k_scanA<<<nb1024, 1024>>>(n);
    k_scanC<<<nb1024, 1024>>>(n, E);
    k_scatter<<<(E + 255) / 256, 256>>>(src, dst, E);

    k_gather_gen<<<(n * 32 + 255) / 256, 256>>>(n);

    int nb64 = (n + 63) / 64;
    k_gemm1<<<nb64, 256, S1>>>(x, W1, b1, n);
    k_gemm2<<<nb64, 128, S2>>>(gamma, beta, W2, b2, n);
    k_gemm3<<<nb64, 256, S3>>>(Wp, bp, Wr, Wl, n);
    k_gather_sage<<<(n * 16 + 255) / 256, 256>>>(n);
    k_final<<<(n * 8 + 255) / 256, 256>>>(bl, Wf, bf, out, n, write_logits);
}

// round 15
// speedup vs baseline: 1.0736x; 1.0363x over previous
#include <cuda_runtime.h>
#include <math.h>

#define NN 50000
#define EE 800000

// ---------------- scratch (device globals; zero-initialized at load) ---------
__device__ unsigned int g_pqh[NN * 64];   // bf16x2 packed (lo=p, hi=q) per channel
__device__ float g_dennum[NN * 128];      // den [0..63], num [64..127]
__device__ float g_h1    [NN * 128];
__device__ float g_x2    [NN * 128];
__device__ float g_xpl   [NN * 64];       // xp @ Wl (pre-multiplied before gather)
__device__ float g_aggr  [NN * 64];
__device__ float g_sum[128], g_sumsq[128];
// CSR
__device__ int g_deg[NN];                 // invariant: zero at kernel_launch entry
__device__ int g_off[NN + 1];
__device__ int g_cur[NN];
__device__ int g_adj[EE];
__device__ int g_bsum[64];

__device__ __forceinline__ float sigmoidf_(float v) { return 1.0f / (1.0f + __expf(-v)); }

typedef unsigned long long ull;

__device__ __forceinline__ ull pack2s(float a) {
    ull r;
    asm("mov.b64 %0, {%1, %1};" : "=l"(r) : "f"(a));
    return r;
}
__device__ __forceinline__ void unpack2(ull v, float& a, float& b) {
    asm("mov.b64 {%0, %1}, %2;" : "=f"(a), "=f"(b) : "l"(v));
}
__device__ __forceinline__ ull fma2(ull a, ull b, ull c) {
    ull r;
    asm("fma.rn.f32x2 %0, %1, %2, %3;" : "=l"(r) : "l"(a), "l"(b), "l"(c));
    return r;
}
// bf16x2 helpers: word = {hi=q, lo=p}
__device__ __forceinline__ unsigned packpq(float p, float q) {
    unsigned r;
    asm("cvt.rn.bf16x2.f32 %0, %1, %2;" : "=r"(r) : "f"(q), "f"(p));
    return r;
}
__device__ __forceinline__ float blo(unsigned u) { return __uint_as_float(u << 16); }
__device__ __forceinline__ float bhi(unsigned u) { return __uint_as_float(u & 0xffff0000u); }

#define AT_S 68

// ---------------- prep (packed pq, sigmoid(x)) + degree histogram -------------
__global__ void k_prep(const float* __restrict__ x, const int* __restrict__ dst,
                       int n, int E) {
    int tid = blockIdx.x * blockDim.x + threadIdx.x;
    if (tid < E) atomicAdd(&g_deg[dst[tid]], 1);
    if (tid >= n * 16) return;
    int nd = tid >> 4, c = tid & 15;
    float4 v = ((const float4*)x)[(size_t)nd * 16 + c];
    float m0 = fmaxf(v.x, 0.f) + 1e-7f;
    float m1 = fmaxf(v.y, 0.f) + 1e-7f;
    float m2 = fmaxf(v.z, 0.f) + 1e-7f;
    float m3 = fmaxf(v.w, 0.f) + 1e-7f;
    float p0 = expf(m0), p1 = expf(m1), p2 = expf(m2), p3 = expf(m3);
    uint4 pk;
    pk.x = packpq(p0, p0 * m0);
    pk.y = packpq(p1, p1 * m1);
    pk.z = packpq(p2, p2 * m2);
    pk.w = packpq(p3, p3 * m3);
    ((uint4*)&g_pqh[(size_t)nd * 64])[c] = pk;
    ((float4*)&g_x2[(size_t)nd * 128])[c] =
        make_float4(sigmoidf_(v.x), sigmoidf_(v.y), sigmoidf_(v.z), sigmoidf_(v.w));
}

// ---------------- scanA ---------------------------------------------------------
__global__ void __launch_bounds__(1024) k_scanA(int n) {
    __shared__ int wp[32];
    int t = threadIdx.x, lane = t & 31, wid = t >> 5;
    int node = blockIdx.x * 1024 + t;
    int d = (node < n) ? g_deg[node] : 0;
    int inc = d;
#pragma unroll
    for (int s = 1; s < 32; s <<= 1) {
        int v = __shfl_up_sync(0xffffffffu, inc, s);
        if (lane >= s) inc += v;
    }
    if (lane == 31) wp[wid] = inc;
    __syncthreads();
    if (wid == 0) {
        int w = wp[lane], winc = w;
#pragma unroll
        for (int s = 1; s < 32; s <<= 1) {
            int v = __shfl_up_sync(0xffffffffu, winc, s);
            if (lane >= s) winc += v;
        }
        wp[lane] = winc - w;
    }
    __syncthreads();
    int ex = wp[wid] + inc - d;
    if (node < n) g_off[node] = ex;
    if (t == 1023) g_bsum[blockIdx.x] = ex + d;
}

// ---------------- scanC: inline combine + zero BN stats -------------------------
__global__ void __launch_bounds__(1024) k_scanC(int n, int E) {
    __shared__ int wsum[2];
    int t = threadIdx.x, b = blockIdx.x;
    int v = (t < b) ? g_bsum[t] : 0;   // b <= 49 < 64
#pragma unroll
    for (int s = 16; s; s >>= 1) v += __shfl_xor_sync(0xffffffffu, v, s);
    if (t == 0) wsum[0] = v;
    if (t == 32) wsum[1] = v;
    if (b == 0) {
        if (t == 0) g_off[n] = E;
        if (t < 128) { g_sum[t] = 0.f; g_sumsq[t] = 0.f; }
    }
    __syncthreads();
    int boff = wsum[0] + wsum[1];
    int node = b * 1024 + t;
    if (node < n) {
        int o = g_off[node] + boff;
        g_off[node] = o;
        g_cur[node] = o;
    }
}

__global__ void k_scatter(const int* __restrict__ src, const int* __restrict__ dst, int E) {
    int e = blockIdx.x * blockDim.x + threadIdx.x;
    if (e >= E) return;
    int pos = atomicAdd(&g_cur[dst[e]], 1);
    g_adj[pos] = src[e];
}

// ---------------- gathers -------------------------------------------------------
// warp-per-dst; lane handles 2 channels (bf16x2 packed); restores g_deg=0
__global__ void k_gather_gen(int n) {
    int w = (blockIdx.x * blockDim.x + threadIdx.x) >> 5;
    int lane = threadIdx.x & 31;
    if (w >= n) return;
    if (lane == 0) g_deg[w] = 0;
    int e = g_off[w], end = g_off[w + 1];
    float p0 = 0.f, q0 = 0.f, p1 = 0.f, q1 = 0.f;
    const uint2* pq = (const uint2*)g_pqh;
    for (; e + 4 <= end; e += 4) {
        int s0 = g_adj[e], s1 = g_adj[e + 1], s2 = g_adj[e + 2], s3 = g_adj[e + 3];
        uint2 u0 = pq[(size_t)s0 * 32 + lane];
        uint2 u1 = pq[(size_t)s1 * 32 + lane];
        uint2 u2 = pq[(size_t)s2 * 32 + lane];
        uint2 u3 = pq[(size_t)s3 * 32 + lane];
        p0 += blo(u0.x) + blo(u1.x) + blo(u2.x) + blo(u3.x);
        q0 += bhi(u0.x) + bhi(u1.x) + bhi(u2.x) + bhi(u3.x);
        p1 += blo(u0.y) + blo(u1.y) + blo(u2.y) + blo(u3.y);
        q1 += bhi(u0.y) + bhi(u1.y) + bhi(u2.y) + bhi(u3.y);
    }
    for (; e < end; e++) {
        int s = g_adj[e];
        uint2 u = pq[(size_t)s * 32 + lane];
        p0 += blo(u.x); q0 += bhi(u.x);
        p1 += blo(u.y); q1 += bhi(u.y);
    }
    // den channels 2*lane, 2*lane+1 ; num at +64
    ((float2*)&g_dennum[(size_t)w * 128])[lane]      = make_float2(p0, p1);
    ((float2*)&g_dennum[(size_t)w * 128 + 64])[lane] = make_float2(q0, q1);
}

// half-warp-per-dst, 64-wide (SAGE xpl, fp32)
__global__ void k_gather_sage(int n) {
    int w = (blockIdx.x * blockDim.x + threadIdx.x) >> 4;
    int lane = threadIdx.x & 15;
    if (w >= n) return;
    int e = g_off[w], end = g_off[w + 1];
    float4 acc = make_float4(0.f, 0.f, 0.f, 0.f);
    for (; e + 4 <= end; e += 4) {
        int s0 = g_adj[e], s1 = g_adj[e + 1], s2 = g_adj[e + 2], s3 = g_adj[e + 3];
        float4 v0 = ((const float4*)g_xpl)[(size_t)s0 * 16 + lane];
        float4 v1 = ((const float4*)g_xpl)[(size_t)s1 * 16 + lane];
        float4 v2 = ((const float4*)g_xpl)[(size_t)s2 * 16 + lane];
        float4 v3 = ((const float4*)g_xpl)[(size_t)s3 * 16 + lane];
        acc.x += v0.x + v1.x + v2.x + v3.x;
        acc.y += v0.y + v1.y + v2.y + v3.y;
        acc.z += v0.z + v1.z + v2.z + v3.z;
        acc.w += v0.w + v1.w + v2.w + v3.w;
    }
    for (; e < end; e++) {
        int s = g_adj[e];
        float4 v = ((const float4*)g_xpl)[(size_t)s * 16 + lane];
        acc.x += v.x; acc.y += v.y; acc.z += v.z; acc.w += v.w;
    }
    ((float4*)g_aggr)[(size_t)w * 16 + lane] = acc;
}

// ============ tiled GEMM bodies (packed f32x2) ===============================
#define DECL_ACC2(CGMASK, NGSHIFT)                                              \
    int cg = tid & (CGMASK);                                                    \
    int ng = tid >> (NGSHIFT);                                                  \
    ull acc2[4][4];                                                             \
    _Pragma("unroll")                                                           \
    for (int i = 0; i < 4; i++)                                                 \
        _Pragma("unroll")                                                       \
        for (int j = 0; j < 4; j++) acc2[i][j] = 0ull;

#define MLBODY2(CIN, COUT)                                                      \
    {                                                                           \
        const float* Ap = At + ng * 4;                                          \
        const ull* Wq = (const ull*)(Ws + cg * 8);                              \
        _Pragma("unroll 8")                                                     \
        for (int k = 0; k < (CIN); k++) {                                       \
            float4 a4 = *(const float4*)&Ap[k * AT_S];                          \
            ulonglong2 wa = *(const ulonglong2*)(Wq + k * ((COUT) / 2));        \
            ulonglong2 wb = *(const ulonglong2*)(Wq + k * ((COUT) / 2) + 2);    \
            ull av[4] = {pack2s(a4.x), pack2s(a4.y), pack2s(a4.z), pack2s(a4.w)};\
            _Pragma("unroll")                                                   \
            for (int i = 0; i < 4; i++) {                                       \
                acc2[i][0] = fma2(av[i], wa.x, acc2[i][0]);                     \
                acc2[i][1] = fma2(av[i], wa.y, acc2[i][1]);                     \
                acc2[i][2] = fma2(av[i], wb.x, acc2[i][2]);                     \
                acc2[i][3] = fma2(av[i], wb.y, acc2[i][3]);                     \
            }                                                                   \
        }                                                                       \
    }

#define UNPACK_ACC()                                                            \
    float acc[4][8];                                                            \
    _Pragma("unroll")                                                           \
    for (int i = 0; i < 4; i++)                                                 \
        _Pragma("unroll")                                                       \
        for (int j = 0; j < 4; j++)                                             \
            unpack2(acc2[i][j], acc[i][2 * j], acc[i][2 * j + 1]);

// ---------------- GEMM1 (+fused column stats) --------------------------------
__global__ void __launch_bounds__(256) k_gemm1(const float* __restrict__ x,
                                               const float* __restrict__ W1,
                                               const float* __restrict__ b1, int n) {
    extern __shared__ float sm[];
    float* Ws = sm;
    float* At = Ws + 64 * 128;
    float* bs = At + 64 * AT_S;
    int tid = threadIdx.x;
    for (int i = tid; i < 2048; i += 256) ((float4*)Ws)[i] = ((const float4*)W1)[i];
    if (tid < 128) bs[tid] = b1[tid];
    int base = blockIdx.x * 64;
    for (int i = tid; i < 1024; i += 256) {
        int ndl = i >> 4, c4 = i & 15;
        int nd = base + ndl;
        float4 in4 = make_float4(0.f, 0.f, 0.f, 0.f);
        if (nd < n) {
            float4 de = ((const float4*)&g_dennum[(size_t)nd * 128])[c4];
            float4 nu = ((const float4*)&g_dennum[(size_t)nd * 128])[16 + c4];
            float4 xv = ((const float4*)x)[(size_t)nd * 16 + c4];
            in4.x = nu.x / (de.x > 0.f ? de.x : 1.f) + xv.x;
            in4.y = nu.y / (de.y > 0.f ? de.y : 1.f) + xv.y;
            in4.z = nu.z / (de.z > 0.f ? de.z : 1.f) + xv.z;
            in4.w = nu.w / (de.w > 0.f ? de.w : 1.f) + xv.w;
        }
        int k0 = c4 * 4;
        At[(k0 + 0) * AT_S + ndl] = in4.x;
        At[(k0 + 1) * AT_S + ndl] = in4.y;
        At[(k0 + 2) * AT_S + ndl] = in4.z;
        At[(k0 + 3) * AT_S + ndl] = in4.w;
    }
    __syncthreads();
    DECL_ACC2(15, 4)
    MLBODY2(64, 128)
    UNPACK_ACC()
    float ls[8], lq[8];
#pragma unroll
    for (int j = 0; j < 8; j++) { ls[j] = 0.f; lq[j] = 0.f; }
#pragma unroll
    for (int i = 0; i < 4; i++) {
        int nd = base + ng * 4 + i;
        if (nd >= n) break;
        float v[8];
#pragma unroll
        for (int j = 0; j < 8; j++) {
            v[j] = acc[i][j] + bs[cg * 8 + j];
            ls[j] += v[j];
            lq[j] += v[j] * v[j];
        }
        float4* o = (float4*)&g_h1[(size_t)nd * 128 + cg * 8];
        o[0] = make_float4(v[0], v[1], v[2], v[3]);
        o[1] = make_float4(v[4], v[5], v[6], v[7]);
    }
    __syncthreads();
    float* ssum = At;
    float* ssq  = At + 128;
    if (tid < 128) { ssum[tid] = 0.f; ssq[tid] = 0.f; }
    __syncthreads();
#pragma unroll
    for (int j = 0; j < 8; j++) {
        atomicAdd(&ssum[cg * 8 + j], ls[j]);
        atomicAdd(&ssq[cg * 8 + j], lq[j]);
    }
    __syncthreads();
    if (tid < 128) {
        atomicAdd(&g_sum[tid], ssum[tid]);
        atomicAdd(&g_sumsq[tid], ssq[tid]);
    }
}

// ---------------- GEMM2 (BN stats inline) -------------------------------------
__global__ void __launch_bounds__(128) k_gemm2(const float* __restrict__ gamma,
                                               const float* __restrict__ beta,
                                               const float* __restrict__ W2,
                                               const float* __restrict__ b2, int n) {
    extern __shared__ float sm[];
    float* Ws = sm;
    float* At = Ws + 128 * 64;
    float* prm = At + 128 * AT_S;
    float* bs = prm + 512;
    int tid = threadIdx.x;
    for (int i = tid; i < 2048; i += 128) ((float4*)Ws)[i] = ((const float4*)W2)[i];
    if (tid < 128) {
        prm[tid]       = gamma[tid];
        prm[128 + tid] = beta[tid];
        float fn = (float)n;
        float mu = g_sum[tid] / fn;
        float var = g_sumsq[tid] / fn - mu * mu;
        prm[256 + tid] = mu;
        prm[384 + tid] = rsqrtf(var + 1e-5f);
    }
    if (tid < 64) bs[tid] = b2[tid];
    __syncthreads();
    int base = blockIdx.x * 64;
    for (int i = tid; i < 2048; i += 128) {
        int ndl = i >> 5, c4 = i & 31;
        int nd = base + ndl;
        float4 v = make_float4(0.f, 0.f, 0.f, 0.f);
        if (nd < n) v = ((const float4*)&g_h1[(size_t)nd * 128])[c4];
        int k0 = c4 * 4;
#pragma unroll
        for (int q = 0; q < 4; q++) {
            float val = (q == 0) ? v.x : (q == 1) ? v.y : (q == 2) ? v.z : v.w;
            int col = k0 + q;
            val = (val - prm[256 + col]) * prm[384 + col] * prm[col] + prm[128 + col];
            At[col * AT_S + ndl] = fmaxf(val, 0.f);
        }
    }
    __syncthreads();
    DECL_ACC2(7, 3)
    MLBODY2(128, 64)
    UNPACK_ACC()
#pragma unroll
    for (int i = 0; i < 4; i++) {
        int nd = base + ng * 4 + i;
        if (nd >= n) break;
        float4 o0 = make_float4(sigmoidf_(acc[i][0] + bs[cg * 8 + 0]),
                                sigmoidf_(acc[i][1] + bs[cg * 8 + 1]),
                                sigmoidf_(acc[i][2] + bs[cg * 8 + 2]),
                                sigmoidf_(acc[i][3] + bs[cg * 8 + 3]));
        float4 o1 = make_float4(sigmoidf_(acc[i][4] + bs[cg * 8 + 4]),
                                sigmoidf_(acc[i][5] + bs[cg * 8 + 5]),
                                sigmoidf_(acc[i][6] + bs[cg * 8 + 6]),
                                sigmoidf_(acc[i][7] + bs[cg * 8 + 7]));
        float4* o = (float4*)&g_x2[(size_t)nd * 128 + 64 + cg * 8];
        o[0] = o0; o[1] = o1;
    }
}

// ---------------- GEMM3: xp = relu(x2@Wp+bp); xpl = xp@Wl ----------------------
__global__ void __launch_bounds__(256) k_gemm3(const float* __restrict__ Wp,
                                               const float* __restrict__ bp,
                                               const float* __restrict__ Wl, int n) {
    extern __shared__ float sm[];
    float* Ws = sm;                // 128*128 (Wp), stage2: first 128*64 = Wl
    float* At = Ws + 128 * 128;    // 128*AT_S
    float* bs = At + 128 * AT_S;   // 128
    int tid = threadIdx.x;
    for (int i = tid; i < 4096; i += 256) ((float4*)Ws)[i] = ((const float4*)Wp)[i];
    if (tid < 128) bs[tid] = bp[tid];
    int base = blockIdx.x * 64;
    for (int i = tid; i < 2048; i += 256) {
        int ndl = i >> 5, c4 = i & 31;
        int nd = base + ndl;
        float4 v = make_float4(0.f, 0.f, 0.f, 0.f);
        if (nd < n) v = ((const float4*)&g_x2[(size_t)nd * 128])[c4];
        int k0 = c4 * 4;
        At[(k0 + 0) * AT_S + ndl] = v.x;
        At[(k0 + 1) * AT_S + ndl] = v.y;
        At[(k0 + 2) * AT_S + ndl] = v.z;
        At[(k0 + 3) * AT_S + ndl] = v.w;
    }
    __syncthreads();
    DECL_ACC2(15, 4)
    MLBODY2(128, 128)
    UNPACK_ACC()
    float xpv[4][8];
#pragma unroll
    for (int i = 0; i < 4; i++)
#pragma unroll
        for (int j = 0; j < 8; j++)
            xpv[i][j] = fmaxf(acc[i][j] + bs[cg * 8 + j], 0.f);
    __syncthreads();
    for (int i = tid; i < 2048; i += 256) ((float4*)Ws)[i] = ((const float4*)Wl)[i];
#pragma unroll
    for (int i = 0; i < 4; i++)
#pragma unroll
        for (int j = 0; j < 8; j++)
            At[(cg * 8 + j) * AT_S + (ng * 4 + i)] = xpv[i][j];
    __syncthreads();
    int cg2 = tid & 7, ng2 = tid >> 3;
    ull a2[2][4];
#pragma unroll
    for (int i = 0; i < 2; i++)
#pragma unroll
        for (int j = 0; j < 4; j++) a2[i][j] = 0ull;
    {
        const float* Ap2 = At + ng2 * 2;
        const ull* Wq2 = (const ull*)(Ws + cg2 * 8);
#pragma unroll 8
        for (int k = 0; k < 128; k++) {
            float2 a = *(const float2*)&Ap2[k * AT_S];
            ulonglong2 wa = *(const ulonglong2*)(Wq2 + k * 32);
            ulonglong2 wb = *(const ulonglong2*)(Wq2 + k * 32 + 2);
            ull av0 = pack2s(a.x), av1 = pack2s(a.y);
            a2[0][0] = fma2(av0, wa.x, a2[0][0]);
            a2[0][1] = fma2(av0, wa.y, a2[0][1]);
            a2[0][2] = fma2(av0, wb.x, a2[0][2]);
            a2[0][3] = fma2(av0, wb.y, a2[0][3]);
            a2[1][0] = fma2(av1, wa.x, a2[1][0]);
            a2[1][1] = fma2(av1, wa.y, a2[1][1]);
            a2[1][2] = fma2(av1, wb.x, a2[1][2]);
            a2[1][3] = fma2(av1, wb.y, a2[1][3]);
        }
    }
#pragma unroll
    for (int i = 0; i < 2; i++) {
        int nd = base + ng2 * 2 + i;
        if (nd >= n) break;
        float v[8];
#pragma unroll
        for (int j = 0; j < 4; j++) unpack2(a2[i][j], v[2 * j], v[2 * j + 1]);
        float4* o = (float4*)&g_xpl[(size_t)nd * 64 + cg2 * 8];
        o[0] = make_float4(v[0], v[1], v[2], v[3]);
        o[1] = make_float4(v[4], v[5], v[6], v[7]);
    }
}

// ---------------- GEMM4: sigmoid(aggr + x2@Wr + bl) @ Wf + bf ------------------
__global__ void __launch_bounds__(128) k_gemm4(const float* __restrict__ Wr,
                                               const float* __restrict__ bl,
                                               const float* __restrict__ Wf,
                                               const float* __restrict__ bf,
                                               float* __restrict__ out,
                                               int n, int write_logits) {
    extern __shared__ float sm[];
    float* Ws = sm;               // 128*64
    float* At = Ws + 128 * 64;    // 128*AT_S
    float* bs = At + 128 * AT_S;  // 64
    float* wf = bs + 64;          // 64
    int tid = threadIdx.x;
    int base = blockIdx.x * 64;
    for (int i = tid; i < 2048; i += 128) ((float4*)Ws)[i] = ((const float4*)Wr)[i];
    if (tid < 64) { bs[tid] = bl[tid]; wf[tid] = Wf[tid]; }
    for (int i = tid; i < 2048; i += 128) {
        int ndl = i >> 5, c4 = i & 31;
        int nd = base + ndl;
        float4 v = make_float4(0.f, 0.f, 0.f, 0.f);
        if (nd < n) v = ((const float4*)&g_x2[(size_t)nd * 128])[c4];
        int k0 = c4 * 4;
        At[(k0 + 0) * AT_S + ndl] = v.x;
        At[(k0 + 1) * AT_S + ndl] = v.y;
        At[(k0 + 2) * AT_S + ndl] = v.z;
        At[(k0 + 3) * AT_S + ndl] = v.w;
    }
    __syncthreads();
    DECL_ACC2(7, 3)
    MLBODY2(128, 64)
    UNPACK_ACC()
    float bf0 = bf[0];
#pragma unroll
    for (int i = 0; i < 4; i++) {
        int nd = base + ng * 4 + i;
        float lp = 0.f;
        if (nd < n) {
            float4 a0 = ((const float4*)&g_aggr[(size_t)nd * 64 + cg * 8])[0];
            float4 a1 = ((const float4*)&g_aggr[(size_t)nd * 64 + cg * 8])[1];
            float av[8] = {a0.x, a0.y, a0.z, a0.w, a1.x, a1.y, a1.z, a1.w};
#pragma unroll
            for (int j = 0; j < 8; j++)
                lp += sigmoidf_(acc[i][j] + av[j] + bs[cg * 8 + j]) * wf[cg * 8 + j];
        }
        lp += __shfl_xor_sync(0xffffffffu, lp, 1);
        lp += __shfl_xor_sync(0xffffffffu, lp, 2);
        lp += __shfl_xor_sync(0xffffffffu, lp, 4);
        if (cg == 0 && nd < n) {
            float logit = lp + bf0;
            out[nd] = sigmoidf_(logit);
            if (write_logits) out[n + nd] = logit;
        }
    }
}

// ---------------- launch --------------------------------------------------------
extern "C" void kernel_launch(void* const* d_in, const int* in_sizes, int n_in,
                              void* d_out, int out_size) {
    const float* x   = (const float*)d_in[0];
    const int*   ei  = (const int*)d_in[1];
    const float* W1  = (const float*)d_in[2];
    const float* b1  = (const float*)d_in[3];
    const float* gamma = (const float*)d_in[4];
    const float* beta  = (const float*)d_in[5];
    const float* W2  = (const float*)d_in[6];
    const float* b2  = (const float*)d_in[7];
    const float* Wp  = (const float*)d_in[8];
    const float* bp  = (const float*)d_in[9];
    const float* Wl  = (const float*)d_in[10];
    const float* bl  = (const float*)d_in[11];
    const float* Wr  = (const float*)d_in[12];
    const float* Wf  = (const float*)d_in[13];
    const float* bf  = (const float*)d_in[14];
    float* out = (float*)d_out;

    int n = in_sizes[0] / 64;
    int E = in_sizes[1] / 2;
    const int* src = ei;
    const int* dst = ei + E;
    int write_logits = (out_size >= 2 * n) ? 1 : 0;

    const int S1 = (64 * 128 + 64 * AT_S + 128) * 4;
    const int S2 = (128 * 64 + 128 * AT_S + 512 + 64) * 4;
    const int S3 = (128 * 128 + 128 * AT_S + 128) * 4;
    const int S4 = (128 * 64 + 128 * AT_S + 128) * 4;
    cudaFuncSetAttribute(k_gemm1, cudaFuncAttributeMaxDynamicSharedMemorySize, S1);
    cudaFuncSetAttribute(k_gemm2, cudaFuncAttributeMaxDynamicSharedMemorySize, S2);
    cudaFuncSetAttribute(k_gemm3, cudaFuncAttributeMaxDynamicSharedMemorySize, S3);
    cudaFuncSetAttribute(k_gemm4, cudaFuncAttributeMaxDynamicSharedMemorySize, S4);

    int tmax = (n * 16 > E) ? n * 16 : E;
    k_prep<<<(tmax + 255) / 256, 256>>>(x, dst, n, E);
    int nb1024 = (n + 1023) / 1024;
    k_scanA<<<nb1024, 1024>>>(n);
    k_scanC<<<nb1024, 1024>>>(n, E);
    k_scatter<<<(E + 255) / 256, 256>>>(src, dst, E);

    k_gather_gen<<<(n * 32 + 255) / 256, 256>>>(n);

    int nb64 = (n + 63) / 64;
    k_gemm1<<<nb64, 256, S1>>>(x, W1, b1, n);
    k_gemm2<<<nb64, 128, S2>>>(gamma, beta, W2, b2, n);
    k_gemm3<<<nb64, 256, S3>>>(Wp, bp, Wl, n);
    k_gather_sage<<<(n * 16 + 255) / 256, 256>>>(n);
    k_gemm4<<<nb64, 128, S4>>>(Wr, bl, Wf, bf, out, n, write_logits);
}

// round 16
// speedup vs baseline: 1.0750x; 1.0013x over previous
#include <cuda_runtime.h>
#include <math.h>

#define NN 50000
#define EE 800000

// ---------------- scratch (device globals; zero-initialized at load) ---------
__device__ unsigned int g_pqh [NN * 64];  // bf16x2 packed (lo=p, hi=q) per channel
__device__ unsigned int g_xplh[NN * 32];  // bf16x2 packed xp@Wl (ch 2j,2j+1 in word j)
__device__ float g_dennum[NN * 128];      // den [0..63], num [64..127]
__device__ float g_h1    [NN * 128];
__device__ float g_x2    [NN * 128];
__device__ float g_aggr  [NN * 64];
__device__ float g_sum[128], g_sumsq[128];
// CSR
__device__ int g_deg[NN];                 // invariant: zero at kernel_launch entry
__device__ int g_off[NN + 1];
__device__ int g_cur[NN];
__device__ int g_adj[EE];
__device__ int g_bsum[64];

__device__ __forceinline__ float sigmoidf_(float v) { return 1.0f / (1.0f + __expf(-v)); }

typedef unsigned long long ull;

__device__ __forceinline__ ull pack2s(float a) {
    ull r;
    asm("mov.b64 %0, {%1, %1};" : "=l"(r) : "f"(a));
    return r;
}
__device__ __forceinline__ void unpack2(ull v, float& a, float& b) {
    asm("mov.b64 {%0, %1}, %2;" : "=f"(a), "=f"(b) : "l"(v));
}
__device__ __forceinline__ ull fma2(ull a, ull b, ull c) {
    ull r;
    asm("fma.rn.f32x2 %0, %1, %2, %3;" : "=l"(r) : "l"(a), "l"(b), "l"(c));
    return r;
}
// bf16x2 helpers: word = {hi, lo}
__device__ __forceinline__ unsigned packbf(float lo, float hi) {
    unsigned r;
    asm("cvt.rn.bf16x2.f32 %0, %1, %2;" : "=r"(r) : "f"(hi), "f"(lo));
    return r;
}
__device__ __forceinline__ float blo(unsigned u) { return __uint_as_float(u << 16); }
__device__ __forceinline__ float bhi(unsigned u) { return __uint_as_float(u & 0xffff0000u); }

#define AT_S 68

// ---------------- prep (packed pq, sigmoid(x)) + degree histogram -------------
__global__ void k_prep(const float* __restrict__ x, const int* __restrict__ dst,
                       int n, int E) {
    int tid = blockIdx.x * blockDim.x + threadIdx.x;
    if (tid < E) atomicAdd(&g_deg[dst[tid]], 1);
    if (tid >= n * 16) return;
    int nd = tid >> 4, c = tid & 15;
    float4 v = ((const float4*)x)[(size_t)nd * 16 + c];
    float m0 = fmaxf(v.x, 0.f) + 1e-7f;
    float m1 = fmaxf(v.y, 0.f) + 1e-7f;
    float m2 = fmaxf(v.z, 0.f) + 1e-7f;
    float m3 = fmaxf(v.w, 0.f) + 1e-7f;
    float p0 = expf(m0), p1 = expf(m1), p2 = expf(m2), p3 = expf(m3);
    uint4 pk;
    pk.x = packbf(p0, p0 * m0);
    pk.y = packbf(p1, p1 * m1);
    pk.z = packbf(p2, p2 * m2);
    pk.w = packbf(p3, p3 * m3);
    ((uint4*)&g_pqh[(size_t)nd * 64])[c] = pk;
    ((float4*)&g_x2[(size_t)nd * 128])[c] =
        make_float4(sigmoidf_(v.x), sigmoidf_(v.y), sigmoidf_(v.z), sigmoidf_(v.w));
}

// ---------------- scanA ---------------------------------------------------------
__global__ void __launch_bounds__(1024) k_scanA(int n) {
    __shared__ int wp[32];
    int t = threadIdx.x, lane = t & 31, wid = t >> 5;
    int node = blockIdx.x * 1024 + t;
    int d = (node < n) ? g_deg[node] : 0;
    int inc = d;
#pragma unroll
    for (int s = 1; s < 32; s <<= 1) {
        int v = __shfl_up_sync(0xffffffffu, inc, s);
        if (lane >= s) inc += v;
    }
    if (lane == 31) wp[wid] = inc;
    __syncthreads();
    if (wid == 0) {
        int w = wp[lane], winc = w;
#pragma unroll
        for (int s = 1; s < 32; s <<= 1) {
            int v = __shfl_up_sync(0xffffffffu, winc, s);
            if (lane >= s) winc += v;
        }
        wp[lane] = winc - w;
    }
    __syncthreads();
    int ex = wp[wid] + inc - d;
    if (node < n) g_off[node] = ex;
    if (t == 1023) g_bsum[blockIdx.x] = ex + d;
}

// ---------------- scanC: inline combine + zero BN stats -------------------------
__global__ void __launch_bounds__(1024) k_scanC(int n, int E) {
    __shared__ int wsum[2];
    int t = threadIdx.x, b = blockIdx.x;
    int v = (t < b) ? g_bsum[t] : 0;   // b <= 49 < 64
#pragma unroll
    for (int s = 16; s; s >>= 1) v += __shfl_xor_sync(0xffffffffu, v, s);
    if (t == 0) wsum[0] = v;
    if (t == 32) wsum[1] = v;
    if (b == 0) {
        if (t == 0) g_off[n] = E;
        if (t < 128) { g_sum[t] = 0.f; g_sumsq[t] = 0.f; }
    }
    __syncthreads();
    int boff = wsum[0] + wsum[1];
    int node = b * 1024 + t;
    if (node < n) {
        int o = g_off[node] + boff;
        g_off[node] = o;
        g_cur[node] = o;
    }
}

__global__ void k_scatter(const int* __restrict__ src, const int* __restrict__ dst, int E) {
    int e = blockIdx.x * blockDim.x + threadIdx.x;
    if (e >= E) return;
    int pos = atomicAdd(&g_cur[dst[e]], 1);
    g_adj[pos] = src[e];
}

// ---------------- gathers -------------------------------------------------------
// warp-per-dst; lane handles 2 channels (bf16x2); restores g_deg=0
__global__ void k_gather_gen(int n) {
    int w = (blockIdx.x * blockDim.x + threadIdx.x) >> 5;
    int lane = threadIdx.x & 31;
    if (w >= n) return;
    if (lane == 0) g_deg[w] = 0;
    int e = g_off[w], end = g_off[w + 1];
    float p0 = 0.f, q0 = 0.f, p1 = 0.f, q1 = 0.f;
    const uint2* pq = (const uint2*)g_pqh;
    for (; e + 4 <= end; e += 4) {
        int s0 = g_adj[e], s1 = g_adj[e + 1], s2 = g_adj[e + 2], s3 = g_adj[e + 3];
        uint2 u0 = pq[(size_t)s0 * 32 + lane];
        uint2 u1 = pq[(size_t)s1 * 32 + lane];
        uint2 u2 = pq[(size_t)s2 * 32 + lane];
        uint2 u3 = pq[(size_t)s3 * 32 + lane];
        p0 += blo(u0.x) + blo(u1.x) + blo(u2.x) + blo(u3.x);
        q0 += bhi(u0.x) + bhi(u1.x) + bhi(u2.x) + bhi(u3.x);
        p1 += blo(u0.y) + blo(u1.y) + blo(u2.y) + blo(u3.y);
        q1 += bhi(u0.y) + bhi(u1.y) + bhi(u2.y) + bhi(u3.y);
    }
    for (; e < end; e++) {
        int s = g_adj[e];
        uint2 u = pq[(size_t)s * 32 + lane];
        p0 += blo(u.x); q0 += bhi(u.x);
        p1 += blo(u.y); q1 += bhi(u.y);
    }
    ((float2*)&g_dennum[(size_t)w * 128])[lane]      = make_float2(p0, p1);
    ((float2*)&g_dennum[(size_t)w * 128 + 64])[lane] = make_float2(q0, q1);
}

// half-warp-per-dst; lane handles 4 channels (2 bf16x2 words)
__global__ void k_gather_sage(int n) {
    int w = (blockIdx.x * blockDim.x + threadIdx.x) >> 4;
    int lane = threadIdx.x & 15;
    if (w >= n) return;
    int e = g_off[w], end = g_off[w + 1];
    float4 acc = make_float4(0.f, 0.f, 0.f, 0.f);
    const uint2* xp = (const uint2*)g_xplh;
    for (; e + 4 <= end; e += 4) {
        int s0 = g_adj[e], s1 = g_adj[e + 1], s2 = g_adj[e + 2], s3 = g_adj[e + 3];
        uint2 u0 = xp[(size_t)s0 * 16 + lane];
        uint2 u1 = xp[(size_t)s1 * 16 + lane];
        uint2 u2 = xp[(size_t)s2 * 16 + lane];
        uint2 u3 = xp[(size_t)s3 * 16 + lane];
        acc.x += blo(u0.x) + blo(u1.x) + blo(u2.x) + blo(u3.x);
        acc.y += bhi(u0.x) + bhi(u1.x) + bhi(u2.x) + bhi(u3.x);
        acc.z += blo(u0.y) + blo(u1.y) + blo(u2.y) + blo(u3.y);
        acc.w += bhi(u0.y) + bhi(u1.y) + bhi(u2.y) + bhi(u3.y);
    }
    for (; e < end; e++) {
        int s = g_adj[e];
        uint2 u = xp[(size_t)s * 16 + lane];
        acc.x += blo(u.x); acc.y += bhi(u.x);
        acc.z += blo(u.y); acc.w += bhi(u.y);
    }
    ((float4*)g_aggr)[(size_t)w * 16 + lane] = acc;
}

// ============ tiled GEMM bodies (packed f32x2) ===============================
#define DECL_ACC2(CGMASK, NGSHIFT)                                              \
    int cg = tid & (CGMASK);                                                    \
    int ng = tid >> (NGSHIFT);                                                  \
    ull acc2[4][4];                                                             \
    _Pragma("unroll")                                                           \
    for (int i = 0; i < 4; i++)                                                 \
        _Pragma("unroll")                                                       \
        for (int j = 0; j < 4; j++) acc2[i][j] = 0ull;

#define MLBODY2(CIN, COUT)                                                      \
    {                                                                           \
        const float* Ap = At + ng * 4;                                          \
        const ull* Wq = (const ull*)(Ws + cg * 8);                              \
        _Pragma("unroll 8")                                                     \
        for (int k = 0; k < (CIN); k++) {                                       \
            float4 a4 = *(const float4*)&Ap[k * AT_S];                          \
            ulonglong2 wa = *(const ulonglong2*)(Wq + k * ((COUT) / 2));        \
            ulonglong2 wb = *(const ulonglong2*)(Wq + k * ((COUT) / 2) + 2);    \
            ull av[4] = {pack2s(a4.x), pack2s(a4.y), pack2s(a4.z), pack2s(a4.w)};\
            _Pragma("unroll")                                                   \
            for (int i = 0; i < 4; i++) {                                       \
                acc2[i][0] = fma2(av[i], wa.x, acc2[i][0]);                     \
                acc2[i][1] = fma2(av[i], wa.y, acc2[i][1]);                     \
                acc2[i][2] = fma2(av[i], wb.x, acc2[i][2]);                     \
                acc2[i][3] = fma2(av[i], wb.y, acc2[i][3]);                     \
            }                                                                   \
        }                                                                       \
    }

#define UNPACK_ACC()                                                            \
    float acc[4][8];                                                            \
    _Pragma("unroll")                                                           \
    for (int i = 0; i < 4; i++)                                                 \
        _Pragma("unroll")                                                       \
        for (int j = 0; j < 4; j++)                                             \
            unpack2(acc2[i][j], acc[i][2 * j], acc[i][2 * j + 1]);

// ---------------- GEMM1 (+fused column stats) --------------------------------
__global__ void __launch_bounds__(256) k_gemm1(const float* __restrict__ x,
                                               const float* __restrict__ W1,
                                               const float* __restrict__ b1, int n) {
    extern __shared__ float sm[];
    float* Ws = sm;
    float* At = Ws + 64 * 128;
    float* bs = At + 64 * AT_S;
    int tid = threadIdx.x;
    for (int i = tid; i < 2048; i += 256) ((float4*)Ws)[i] = ((const float4*)W1)[i];
    if (tid < 128) bs[tid] = b1[tid];
    int base = blockIdx.x * 64;
    for (int i = tid; i < 1024; i += 256) {
        int ndl = i >> 4, c4 = i & 15;
        int nd = base + ndl;
        float4 in4 = make_float4(0.f, 0.f, 0.f, 0.f);
        if (nd < n) {
            float4 de = ((const float4*)&g_dennum[(size_t)nd * 128])[c4];
            float4 nu = ((const float4*)&g_dennum[(size_t)nd * 128])[16 + c4];
            float4 xv = ((const float4*)x)[(size_t)nd * 16 + c4];
            in4.x = nu.x / (de.x > 0.f ? de.x : 1.f) + xv.x;
            in4.y = nu.y / (de.y > 0.f ? de.y : 1.f) + xv.y;
            in4.z = nu.z / (de.z > 0.f ? de.z : 1.f) + xv.z;
            in4.w = nu.w / (de.w > 0.f ? de.w : 1.f) + xv.w;
        }
        int k0 = c4 * 4;
        At[(k0 + 0) * AT_S + ndl] = in4.x;
        At[(k0 + 1) * AT_S + ndl] = in4.y;
        At[(k0 + 2) * AT_S + ndl] = in4.z;
        At[(k0 + 3) * AT_S + ndl] = in4.w;
    }
    __syncthreads();
    DECL_ACC2(15, 4)
    MLBODY2(64, 128)
    UNPACK_ACC()
    float ls[8], lq[8];
#pragma unroll
    for (int j = 0; j < 8; j++) { ls[j] = 0.f; lq[j] = 0.f; }
#pragma unroll
    for (int i = 0; i < 4; i++) {
        int nd = base + ng * 4 + i;
        if (nd >= n) break;
        float v[8];
#pragma unroll
        for (int j = 0; j < 8; j++) {
            v[j] = acc[i][j] + bs[cg * 8 + j];
            ls[j] += v[j];
            lq[j] += v[j] * v[j];
        }
        float4* o = (float4*)&g_h1[(size_t)nd * 128 + cg * 8];
        o[0] = make_float4(v[0], v[1], v[2], v[3]);
        o[1] = make_float4(v[4], v[5], v[6], v[7]);
    }
    __syncthreads();
    float* ssum = At;
    float* ssq  = At + 128;
    if (tid < 128) { ssum[tid] = 0.f; ssq[tid] = 0.f; }
    __syncthreads();
#pragma unroll
    for (int j = 0; j < 8; j++) {
        atomicAdd(&ssum[cg * 8 + j], ls[j]);
        atomicAdd(&ssq[cg * 8 + j], lq[j]);
    }
    __syncthreads();
    if (tid < 128) {
        atomicAdd(&g_sum[tid], ssum[tid]);
        atomicAdd(&g_sumsq[tid], ssq[tid]);
    }
}

// ---------------- GEMM2 (BN stats inline) -------------------------------------
__global__ void __launch_bounds__(128) k_gemm2(const float* __restrict__ gamma,
                                               const float* __restrict__ beta,
                                               const float* __restrict__ W2,
                                               const float* __restrict__ b2, int n) {
    extern __shared__ float sm[];
    float* Ws = sm;
    float* At = Ws + 128 * 64;
    float* prm = At + 128 * AT_S;
    float* bs = prm + 512;
    int tid = threadIdx.x;
    for (int i = tid; i < 2048; i += 128) ((float4*)Ws)[i] = ((const float4*)W2)[i];
    if (tid < 128) {
        prm[tid]       = gamma[tid];
        prm[128 + tid] = beta[tid];
        float fn = (float)n;
        float mu = g_sum[tid] / fn;
        float var = g_sumsq[tid] / fn - mu * mu;
        prm[256 + tid] = mu;
        prm[384 + tid] = rsqrtf(var + 1e-5f);
    }
    if (tid < 64) bs[tid] = b2[tid];
    __syncthreads();
    int base = blockIdx.x * 64;
    for (int i = tid; i < 2048; i += 128) {
        int ndl = i >> 5, c4 = i & 31;
        int nd = base + ndl;
        float4 v = make_float4(0.f, 0.f, 0.f, 0.f);
        if (nd < n) v = ((const float4*)&g_h1[(size_t)nd * 128])[c4];
        int k0 = c4 * 4;
#pragma unroll
        for (int q = 0; q < 4; q++) {
            float val = (q == 0) ? v.x : (q == 1) ? v.y : (q == 2) ? v.z : v.w;
            int col = k0 + q;
            val = (val - prm[256 + col]) * prm[384 + col] * prm[col] + prm[128 + col];
            At[col * AT_S + ndl] = fmaxf(val, 0.f);
        }
    }
    __syncthreads();
    DECL_ACC2(7, 3)
    MLBODY2(128, 64)
    UNPACK_ACC()
#pragma unroll
    for (int i = 0; i < 4; i++) {
        int nd = base + ng * 4 + i;
        if (nd >= n) break;
        float4 o0 = make_float4(sigmoidf_(acc[i][0] + bs[cg * 8 + 0]),
                                sigmoidf_(acc[i][1] + bs[cg * 8 + 1]),
                                sigmoidf_(acc[i][2] + bs[cg * 8 + 2]),
                                sigmoidf_(acc[i][3] + bs[cg * 8 + 3]));
        float4 o1 = make_float4(sigmoidf_(acc[i][4] + bs[cg * 8 + 4]),
                                sigmoidf_(acc[i][5] + bs[cg * 8 + 5]),
                                sigmoidf_(acc[i][6] + bs[cg * 8 + 6]),
                                sigmoidf_(acc[i][7] + bs[cg * 8 + 7]));
        float4* o = (float4*)&g_x2[(size_t)nd * 128 + 64 + cg * 8];
        o[0] = o0; o[1] = o1;
    }
}

// ---------------- GEMM3: xp = relu(x2@Wp+bp); xpl = xp@Wl (bf16 out) -----------
__global__ void __launch_bounds__(256) k_gemm3(const float* __restrict__ Wp,
                                               const float* __restrict__ bp,
                                               const float* __restrict__ Wl, int n) {
    extern __shared__ float sm[];
    float* Ws = sm;                // 128*128 (Wp), stage2: first 128*64 = Wl
    float* At = Ws + 128 * 128;    // 128*AT_S
    float* bs = At + 128 * AT_S;   // 128
    int tid = threadIdx.x;
    for (int i = tid; i < 4096; i += 256) ((float4*)Ws)[i] = ((const float4*)Wp)[i];
    if (tid < 128) bs[tid] = bp[tid];
    int base = blockIdx.x * 64;
    for (int i = tid; i < 2048; i += 256) {
        int ndl = i >> 5, c4 = i & 31;
        int nd = base + ndl;
        float4 v = make_float4(0.f, 0.f, 0.f, 0.f);
        if (nd < n) v = ((const float4*)&g_x2[(size_t)nd * 128])[c4];
        int k0 = c4 * 4;
        At[(k0 + 0) * AT_S + ndl] = v.x;
        At[(k0 + 1) * AT_S + ndl] = v.y;
        At[(k0 + 2) * AT_S + ndl] = v.z;
        At[(k0 + 3) * AT_S + ndl] = v.w;
    }
    __syncthreads();
    DECL_ACC2(15, 4)
    MLBODY2(128, 128)
    UNPACK_ACC()
    float xpv[4][8];
#pragma unroll
    for (int i = 0; i < 4; i++)
#pragma unroll
        for (int j = 0; j < 8; j++)
            xpv[i][j] = fmaxf(acc[i][j] + bs[cg * 8 + j], 0.f);
    __syncthreads();
    for (int i = tid; i < 2048; i += 256) ((float4*)Ws)[i] = ((const float4*)Wl)[i];
#pragma unroll
    for (int i = 0; i < 4; i++)
#pragma unroll
        for (int j = 0; j < 8; j++)
            At[(cg * 8 + j) * AT_S + (ng * 4 + i)] = xpv[i][j];
    __syncthreads();
    int cg2 = tid & 7, ng2 = tid >> 3;
    ull a2[2][4];
#pragma unroll
    for (int i = 0; i < 2; i++)
#pragma unroll
        for (int j = 0; j < 4; j++) a2[i][j] = 0ull;
    {
        const float* Ap2 = At + ng2 * 2;
        const ull* Wq2 = (const ull*)(Ws + cg2 * 8);
#pragma unroll 8
        for (int k = 0; k < 128; k++) {
            float2 a = *(const float2*)&Ap2[k * AT_S];
            ulonglong2 wa = *(const ulonglong2*)(Wq2 + k * 32);
            ulonglong2 wb = *(const ulonglong2*)(Wq2 + k * 32 + 2);
            ull av0 = pack2s(a.x), av1 = pack2s(a.y);
            a2[0][0] = fma2(av0, wa.x, a2[0][0]);
            a2[0][1] = fma2(av0, wa.y, a2[0][1]);
            a2[0][2] = fma2(av0, wb.x, a2[0][2]);
            a2[0][3] = fma2(av0, wb.y, a2[0][3]);
            a2[1][0] = fma2(av1, wa.x, a2[1][0]);
            a2[1][1] = fma2(av1, wa.y, a2[1][1]);
            a2[1][2] = fma2(av1, wb.x, a2[1][2]);
            a2[1][3] = fma2(av1, wb.y, a2[1][3]);
        }
    }
#pragma unroll
    for (int i = 0; i < 2; i++) {
        int nd = base + ng2 * 2 + i;
        if (nd >= n) break;
        float v[8];
#pragma unroll
        for (int j = 0; j < 4; j++) unpack2(a2[i][j], v[2 * j], v[2 * j + 1]);
        uint2 pk0, pk1;
        pk0.x = packbf(v[0], v[1]); pk0.y = packbf(v[2], v[3]);
        pk1.x = packbf(v[4], v[5]); pk1.y = packbf(v[6], v[7]);
        uint2* o = (uint2*)&g_xplh[(size_t)nd * 32 + cg2 * 4];
        o[0] = pk0; o[1] = pk1;
    }
}

// ---------------- GEMM4: sigmoid(aggr + x2@Wr + bl) @ Wf + bf ------------------
__global__ void __launch_bounds__(128) k_gemm4(const float* __restrict__ Wr,
                                               const float* __restrict__ bl,
                                               const float* __restrict__ Wf,
                                               const float* __restrict__ bf,
                                               float* __restrict__ out,
                                               int n, int write_logits) {
    extern __shared__ float sm[];
    float* Ws = sm;               // 128*64
    float* At = Ws + 128 * 64;    // 128*AT_S
    float* bs = At + 128 * AT_S;  // 64
    float* wf = bs + 64;          // 64
    int tid = threadIdx.x;
    int base = blockIdx.x * 64;
    for (int i = tid; i < 2048; i += 128) ((float4*)Ws)[i] = ((const float4*)Wr)[i];
    if (tid < 64) { bs[tid] = bl[tid]; wf[tid] = Wf[tid]; }
    for (int i = tid; i < 2048; i += 128) {
        int ndl = i >> 5, c4 = i & 31;
        int nd = base + ndl;
        float4 v = make_float4(0.f, 0.f, 0.f, 0.f);
        if (nd < n) v = ((const float4*)&g_x2[(size_t)nd * 128])[c4];
        int k0 = c4 * 4;
        At[(k0 + 0) * AT_S + ndl] = v.x;
        At[(k0 + 1) * AT_S + ndl] = v.y;
        At[(k0 + 2) * AT_S + ndl] = v.z;
        At[(k0 + 3) * AT_S + ndl] = v.w;
    }
    __syncthreads();
    DECL_ACC2(7, 3)
    MLBODY2(128, 64)
    UNPACK_ACC()
    float bf0 = bf[0];
#pragma unroll
    for (int i = 0; i < 4; i++) {
        int nd = base + ng * 4 + i;
        float lp = 0.f;
        if (nd < n) {
            float4 a0 = ((const float4*)&g_aggr[(size_t)nd * 64 + cg * 8])[0];
            float4 a1 = ((const float4*)&g_aggr[(size_t)nd * 64 + cg * 8])[1];
            float av[8] = {a0.x, a0.y, a0.z, a0.w, a1.x, a1.y, a1.z, a1.w};
#pragma unroll
            for (int j = 0; j < 8; j++)
                lp += sigmoidf_(acc[i][j] + av[j] + bs[cg * 8 + j]) * wf[cg * 8 + j];
        }
        lp += __shfl_xor_sync(0xffffffffu, lp, 1);
        lp += __shfl_xor_sync(0xffffffffu, lp, 2);
        lp += __shfl_xor_sync(0xffffffffu, lp, 4);
        if (cg == 0 && nd < n) {
            float logit = lp + bf0;
            out[nd] = sigmoidf_(logit);
            if (write_logits) out[n + nd] = logit;
        }
    }
}

// ---------------- launch --------------------------------------------------------
extern "C" void kernel_launch(void* const* d_in, const int* in_sizes, int n_in,
                              void* d_out, int out_size) {
    const float* x   = (const float*)d_in[0];
    const int*   ei  = (const int*)d_in[1];
    const float* W1  = (const float*)d_in[2];
    const float* b1  = (const float*)d_in[3];
    const float* gamma = (const float*)d_in[4];
    const float* beta  = (const float*)d_in[5];
    const float* W2  = (const float*)d_in[6];
    const float* b2  = (const float*)d_in[7];
    const float* Wp  = (const float*)d_in[8];
    const float* bp  = (const float*)d_in[9];
    const float* Wl  = (const float*)d_in[10];
    const float* bl  = (const float*)d_in[11];
    const float* Wr  = (const float*)d_in[12];
    const float* Wf  = (const float*)d_in[13];
    const float* bf  = (const float*)d_in[14];
    float* out = (float*)d_out;

    int n = in_sizes[0] / 64;
    int E = in_sizes[1] / 2;
    const int* src = ei;
    const int* dst = ei + E;
    int write_logits = (out_size >= 2 * n) ? 1 : 0;

    const int S1 = (64 * 128 + 64 * AT_S + 128) * 4;
    const int S2 = (128 * 64 + 128 * AT_S + 512 + 64) * 4;
    const int S3 = (128 * 128 + 128 * AT_S + 128) * 4;
    const int S4 = (128 * 64 + 128 * AT_S + 128) * 4;
    cudaFuncSetAttribute(k_gemm1, cudaFuncAttributeMaxDynamicSharedMemorySize, S1);
    cudaFuncSetAttribute(k_gemm2, cudaFuncAttributeMaxDynamicSharedMemorySize, S2);
    cudaFuncSetAttribute(k_gemm3, cudaFuncAttributeMaxDynamicSharedMemorySize, S3);
    cudaFuncSetAttribute(k_gemm4, cudaFuncAttributeMaxDynamicSharedMemorySize, S4);

    int tmax = (n * 16 > E) ? n * 16 : E;
    k_prep<<<(tmax + 255) / 256, 256>>>(x, dst, n, E);
    int nb1024 = (n + 1023) / 1024;
    k_scanA<<<nb1024, 1024>>>(n);
    k_scanC<<<nb1024, 1024>>>(n, E);
    k_scatter<<<(E + 255) / 256, 256>>>(src, dst, E);

    k_gather_gen<<<(n * 32 + 255) / 256, 256>>>(n);

    int nb64 = (n + 63) / 64;
    k_gemm1<<<nb64, 256, S1>>>(x, W1, b1, n);
    k_gemm2<<<nb64, 128, S2>>>(gamma, beta, W2, b2, n);
    k_gemm3<<<nb64, 256, S3>>>(Wp, bp, Wl, n);
    k_gather_sage<<<(n * 16 + 255) / 256, 256>>>(n);
    k_gemm4<<<nb64, 128, S4>>>(Wr, bl, Wf, bf, out, n, write_logits);
}